// round 1
// baseline (speedup 1.0000x reference)
#include <cuda_runtime.h>
#include <math.h>

// ---------------------------------------------------------------------------
// Problem dimensions (compile-time)
// ---------------------------------------------------------------------------
#define LNUM 8
#define BB   8
#define TT   1024
#define CC   768
#define HH   12
#define DD   64
#define VV   1024
#define FFF  3072
#define BT   (BB*TT)   // 8192

// ---------------------------------------------------------------------------
// Scratch (static device globals; no allocation allowed)
// ---------------------------------------------------------------------------
__device__ float g_h  [BT * CC];       // residual stream        (25.2 MB)
__device__ float g_qkv[BT * 3 * CC];   // qkv projections        (75.5 MB)
__device__ float g_att[BT * CC];       // attention output       (25.2 MB)
__device__ float g_mid[BT * FFF];      // FFN intermediate      (100.7 MB)
__device__ float g_tmp[BT * CC];       // FFN output             (25.2 MB)

// ---------------------------------------------------------------------------
// Embedding: h[b,t,:] = embed[x[b,t],:] + pos[t,:]
// ---------------------------------------------------------------------------
__global__ void __launch_bounds__(192) embed_kernel(
    const int* __restrict__ x, const float* __restrict__ emb,
    const float* __restrict__ pos, float* __restrict__ h)
{
    const int bt  = blockIdx.x;
    const int tok = x[bt];
    const int t   = bt & (TT - 1);
    const float4* e4 = (const float4*)(emb + (size_t)tok * CC);
    const float4* p4 = (const float4*)(pos + (size_t)t   * CC);
    float4*       h4 = (float4*)(h + (size_t)bt * CC);
    const int i = threadIdx.x;                 // 0..191  (CC/4 = 192)
    float4 a = e4[i], b = p4[i];
    h4[i] = make_float4(a.x + b.x, a.y + b.y, a.z + b.z, a.w + b.w);
}

// ---------------------------------------------------------------------------
// Exact GELU (approximate=False): 0.5*x*(1+erf(x/sqrt(2)))
// ---------------------------------------------------------------------------
__device__ __forceinline__ float gelu_f(float x)
{
    return 0.5f * x * (1.0f + erff(x * 0.70710678118654752f));
}

// ---------------------------------------------------------------------------
// SGEMM: C = epi(A[MxK] @ B[KxN] + bias[N]) ; all row-major.
// 128x128 block tile, 256 threads, 8x8 microtile, BK=8, global prefetch.
// All M,N multiples of 128 and K multiples of 8 in this network -> no guards.
// EPI: 0 = identity, 1 = exact GELU.
// ---------------------------------------------------------------------------
template<int EPI>
__global__ void __launch_bounds__(256) sgemm_kernel(
    const float* __restrict__ A, const float* __restrict__ B,
    const float* __restrict__ bias, float* __restrict__ C,
    int M, int N, int K)
{
    __shared__ float As[8][128];   // transposed: As[k][m]
    __shared__ float Bs[8][128];   // natural:    Bs[k][n]

    const int tid = threadIdx.x;
    const int bm  = blockIdx.y << 7;
    const int bn  = blockIdx.x << 7;
    const int tx  = tid & 15;       // col group
    const int ty  = tid >> 4;       // row group

    // staging assignment
    const int am  = tid >> 1;             // 0..127 : A row within tile
    const int ak  = (tid & 1) << 2;       // 0 or 4 : A k offset
    const int bk  = tid >> 5;             // 0..7   : B k row
    const int bn4 = (tid & 31) << 2;      // 0..124 : B col

    const float* Ap = A + (size_t)(bm + am) * K + ak;
    const float* Bp = B + (size_t)bk * N + bn + bn4;

    float acc[8][8];
#pragma unroll
    for (int i = 0; i < 8; i++)
#pragma unroll
        for (int j = 0; j < 8; j++) acc[i][j] = 0.f;

    const int nk = K >> 3;
    float4 ra = *(const float4*)Ap;
    float4 rb = *(const float4*)Bp;

    for (int kt = 0; kt < nk; kt++) {
        As[ak + 0][am] = ra.x; As[ak + 1][am] = ra.y;
        As[ak + 2][am] = ra.z; As[ak + 3][am] = ra.w;
        *(float4*)&Bs[bk][bn4] = rb;
        __syncthreads();
        if (kt + 1 < nk) {
            ra = *(const float4*)(Ap + (size_t)(kt + 1) * 8);
            rb = *(const float4*)(Bp + (size_t)(kt + 1) * 8 * N);
        }
#pragma unroll
        for (int k = 0; k < 8; k++) {
            float4 a0 = *(const float4*)&As[k][(ty << 2)];
            float4 a1 = *(const float4*)&As[k][64 + (ty << 2)];
            float4 b0 = *(const float4*)&Bs[k][(tx << 2)];
            float4 b1 = *(const float4*)&Bs[k][64 + (tx << 2)];
            float av[8] = {a0.x, a0.y, a0.z, a0.w, a1.x, a1.y, a1.z, a1.w};
            float bv[8] = {b0.x, b0.y, b0.z, b0.w, b1.x, b1.y, b1.z, b1.w};
#pragma unroll
            for (int i = 0; i < 8; i++)
#pragma unroll
                for (int j = 0; j < 8; j++)
                    acc[i][j] = fmaf(av[i], bv[j], acc[i][j]);
        }
        __syncthreads();
    }

    // epilogue: thread owns rows {ty*4..+3, 64+ty*4..+3}, cols {tx*4..+3, 64+tx*4..+3}
    float bia[8];
#pragma unroll
    for (int j = 0; j < 8; j++) {
        int col = bn + ((j < 4) ? (tx << 2) + j : 64 + (tx << 2) + (j - 4));
        bia[j] = bias[col];
    }
#pragma unroll
    for (int i = 0; i < 8; i++) {
        int row = bm + ((i < 4) ? (ty << 2) + i : 64 + (ty << 2) + (i - 4));
        float* cp = C + (size_t)row * N + bn;
        float v[8];
#pragma unroll
        for (int j = 0; j < 8; j++) {
            float t = acc[i][j] + bia[j];
            v[j] = (EPI == 1) ? gelu_f(t) : t;
        }
        *(float4*)(cp + (tx << 2))      = make_float4(v[0], v[1], v[2], v[3]);
        *(float4*)(cp + 64 + (tx << 2)) = make_float4(v[4], v[5], v[6], v[7]);
    }
}

// ---------------------------------------------------------------------------
// Fused causal flash attention (D=64). One block = (b, h, 64-query tile).
// qkv layout: (B,T,3C), split order K | Q | V (per source). Online softmax.
// Shared: Qt [d][r] (transposed), KP = K tile [d][c] aliased with P [r][c],
//         Vs [c][d]. 3 * 16 KB = 48 KB static smem.
// ---------------------------------------------------------------------------
__global__ void __launch_bounds__(256) attn_kernel(
    const float* __restrict__ qkv, float* __restrict__ out)
{
    __shared__ float Qt[64][64];
    __shared__ float KP[64][64];
    __shared__ float Vs[64][64];

    const int tid   = threadIdx.x;
    const int qtile = blockIdx.x;          // 0..15
    const int bh    = blockIdx.y;          // 0..95
    const int b     = bh / HH;
    const int h     = bh % HH;
    const int qb    = qtile << 6;
    const float* base = qkv + (size_t)b * TT * 3 * CC;

    const int cc   = tid & 63;             // token within tile (staging)
    const int dblk = tid >> 6;             // 0..3

    // stage Q transposed: Qt[d][r]
    {
        const float* Qg = base + (size_t)(qb + cc) * 3 * CC + CC + h * DD;
#pragma unroll
        for (int i = 0; i < 4; i++) {
            int d0 = (dblk + (i << 2)) << 2;
            float4 g = *(const float4*)(Qg + d0);
            Qt[d0 + 0][cc] = g.x; Qt[d0 + 1][cc] = g.y;
            Qt[d0 + 2][cc] = g.z; Qt[d0 + 3][cc] = g.w;
        }
    }

    const int tx = tid & 15, ty = tid >> 4;
    float m[4], l[4], O[4][4];
#pragma unroll
    for (int i = 0; i < 4; i++) {
        m[i] = -1e30f; l[i] = 0.f;
#pragma unroll
        for (int j = 0; j < 4; j++) O[i][j] = 0.f;
    }

    for (int kt = 0; kt <= qtile; kt++) {
        const int kb = kt << 6;
        __syncthreads();   // prior iter's PV reads done; Qt visible on iter 0
        // stage K transposed: KP[d][c]
        {
            const float* Kg = base + (size_t)(kb + cc) * 3 * CC + h * DD;
#pragma unroll
            for (int i = 0; i < 4; i++) {
                int d0 = (dblk + (i << 2)) << 2;
                float4 g = *(const float4*)(Kg + d0);
                KP[d0 + 0][cc] = g.x; KP[d0 + 1][cc] = g.y;
                KP[d0 + 2][cc] = g.z; KP[d0 + 3][cc] = g.w;
            }
        }
        // stage V natural: Vs[c][d]
#pragma unroll
        for (int i = 0; i < 4; i++) {
            int f  = tid + (i << 8);
            int vc = f >> 4;
            int vd = (f & 15) << 2;
            float4 g = *(const float4*)(base + (size_t)(kb + vc) * 3 * CC
                                        + 2 * CC + h * DD + vd);
            *(float4*)&Vs[vc][vd] = g;
        }
        __syncthreads();

        // S = (Q K^T) * scale  (4x4 microtile per thread)
        float S[4][4];
#pragma unroll
        for (int i = 0; i < 4; i++)
#pragma unroll
            for (int j = 0; j < 4; j++) S[i][j] = 0.f;
#pragma unroll 8
        for (int d = 0; d < 64; d++) {
            float4 a  = *(const float4*)&Qt[d][(ty << 2)];
            float4 bq = *(const float4*)&KP[d][(tx << 2)];
            float av[4] = {a.x, a.y, a.z, a.w};
            float bv[4] = {bq.x, bq.y, bq.z, bq.w};
#pragma unroll
            for (int i = 0; i < 4; i++)
#pragma unroll
                for (int j = 0; j < 4; j++)
                    S[i][j] = fmaf(av[i], bv[j], S[i][j]);
        }
        const float scale = 0.125f;   // 1/sqrt(64)
        if (kt == qtile) {
#pragma unroll
            for (int i = 0; i < 4; i++) {
                int q = qb + (ty << 2) + i;
#pragma unroll
                for (int j = 0; j < 4; j++) {
                    int kk = kb + (tx << 2) + j;
                    S[i][j] = (kk <= q) ? S[i][j] * scale : -1e30f;
                }
            }
        } else {
#pragma unroll
            for (int i = 0; i < 4; i++)
#pragma unroll
                for (int j = 0; j < 4; j++) S[i][j] *= scale;
        }

        // online softmax update (row group = 16 lanes sharing ty)
        float alpha[4];
#pragma unroll
        for (int i = 0; i < 4; i++) {
            float pm = fmaxf(fmaxf(S[i][0], S[i][1]), fmaxf(S[i][2], S[i][3]));
#pragma unroll
            for (int o = 1; o < 16; o <<= 1)
                pm = fmaxf(pm, __shfl_xor_sync(0xffffffffu, pm, o));
            float mn = fmaxf(m[i], pm);
            alpha[i] = __expf(m[i] - mn);
            float rs = 0.f;
#pragma unroll
            for (int j = 0; j < 4; j++) { S[i][j] = __expf(S[i][j] - mn); rs += S[i][j]; }
#pragma unroll
            for (int o = 1; o < 16; o <<= 1)
                rs += __shfl_xor_sync(0xffffffffu, rs, o);
            l[i] = l[i] * alpha[i] + rs;
            m[i] = mn;
#pragma unroll
            for (int j = 0; j < 4; j++) O[i][j] *= alpha[i];
        }

        __syncthreads();   // everyone done reading KP (K tile)
        // write P into KP as [r][c]
#pragma unroll
        for (int i = 0; i < 4; i++)
            *(float4*)&KP[(ty << 2) + i][(tx << 2)] =
                make_float4(S[i][0], S[i][1], S[i][2], S[i][3]);
        __syncthreads();

        // O += P @ V  (thread owns rows ty*4.., output dims tx*4..)
#pragma unroll 4
        for (int c = 0; c < 64; c++) {
            float4 v = *(const float4*)&Vs[c][(tx << 2)];
            float vv[4] = {v.x, v.y, v.z, v.w};
#pragma unroll
            for (int i = 0; i < 4; i++) {
                float p = KP[(ty << 2) + i][c];
#pragma unroll
                for (int j = 0; j < 4; j++)
                    O[i][j] = fmaf(p, vv[j], O[i][j]);
            }
        }
    }

    // write normalized output: (B,T,C) with head h at cols h*64..
#pragma unroll
    for (int i = 0; i < 4; i++) {
        float inv = 1.0f / l[i];
        float* op = out + ((size_t)b * TT + qb + (ty << 2) + i) * CC
                        + h * DD + (tx << 2);
        *(float4*)op = make_float4(O[i][0] * inv, O[i][1] * inv,
                                   O[i][2] * inv, O[i][3] * inv);
    }
}

// ---------------------------------------------------------------------------
// Fused LayerNorm + residual add: h[row] += LN(y[row]) * g + beta
// One block (256 threads) per row of 768.
// ---------------------------------------------------------------------------
__global__ void __launch_bounds__(256) ln_res_kernel(
    const float* __restrict__ y, const float* __restrict__ g,
    const float* __restrict__ be, float* __restrict__ h)
{
    __shared__ float red1[8];
    __shared__ float red2[8];
    const int row = blockIdx.x;
    const int tid = threadIdx.x;
    const float* yr = y + (size_t)row * CC;

    float v0 = yr[tid], v1 = yr[tid + 256], v2 = yr[tid + 512];
    float s = v0 + v1 + v2;
#pragma unroll
    for (int o = 16; o; o >>= 1) s += __shfl_xor_sync(0xffffffffu, s, o);
    if ((tid & 31) == 0) red1[tid >> 5] = s;
    __syncthreads();
    float tot = 0.f;
#pragma unroll
    for (int i = 0; i < 8; i++) tot += red1[i];
    float mu = tot * (1.0f / 768.0f);

    float d0 = v0 - mu, d1 = v1 - mu, d2 = v2 - mu;
    float q = d0 * d0 + d1 * d1 + d2 * d2;
#pragma unroll
    for (int o = 16; o; o >>= 1) q += __shfl_xor_sync(0xffffffffu, q, o);
    if ((tid & 31) == 0) red2[tid >> 5] = q;
    __syncthreads();
    float qt = 0.f;
#pragma unroll
    for (int i = 0; i < 8; i++) qt += red2[i];
    float rstd = rsqrtf(qt * (1.0f / 768.0f) + 1e-5f);

    float* hr = h + (size_t)row * CC;
    hr[tid]       += d0 * rstd * g[tid]       + be[tid];
    hr[tid + 256] += d1 * rstd * g[tid + 256] + be[tid + 256];
    hr[tid + 512] += d2 * rstd * g[tid + 512] + be[tid + 512];
}

// ---------------------------------------------------------------------------
// Launch: embed -> 8x[qkv GEMM, attn, FFNa(gelu,proj), LN+res, FFNb, LN+res]
//         -> lm head GEMM into d_out
// ---------------------------------------------------------------------------
extern "C" void kernel_launch(void* const* d_in, const int* in_sizes, int n_in,
                              void* d_out, int out_size)
{
    const int*   x     = (const int*)  d_in[0];
    const float* embed = (const float*)d_in[1];
    const float* pos   = (const float*)d_in[2];
    const float* Wqkv  = (const float*)d_in[3];
    const float* bqkv  = (const float*)d_in[4];
    const float* W1a   = (const float*)d_in[5];
    const float* b1a   = (const float*)d_in[6];
    const float* W2a   = (const float*)d_in[7];
    const float* b2a   = (const float*)d_in[8];
    const float* g1    = (const float*)d_in[9];
    const float* beta1 = (const float*)d_in[10];
    const float* W1b   = (const float*)d_in[11];
    const float* b1b   = (const float*)d_in[12];
    const float* W2b   = (const float*)d_in[13];
    const float* b2b   = (const float*)d_in[14];
    const float* g2    = (const float*)d_in[15];
    const float* beta2 = (const float*)d_in[16];
    const float* lmW   = (const float*)d_in[17];
    const float* lmb   = (const float*)d_in[18];
    float* out = (float*)d_out;

    float *h, *qkvb, *att, *mid, *tmp;
    cudaGetSymbolAddress((void**)&h,    g_h);
    cudaGetSymbolAddress((void**)&qkvb, g_qkv);
    cudaGetSymbolAddress((void**)&att,  g_att);
    cudaGetSymbolAddress((void**)&mid,  g_mid);
    cudaGetSymbolAddress((void**)&tmp,  g_tmp);

    embed_kernel<<<BT, 192>>>(x, embed, pos, h);

    const dim3 grid_qkv (3 * CC / 128, BT / 128);
    const dim3 grid_ffn1(FFF / 128,    BT / 128);
    const dim3 grid_ffn2(CC / 128,     BT / 128);
    const dim3 grid_lm  (VV / 128,     BT / 128);
    const dim3 grid_attn(TT / 64, BB * HH);

    for (int l = 0; l < LNUM; l++) {
        sgemm_kernel<0><<<grid_qkv, 256>>>(
            h, Wqkv + (size_t)l * CC * 3 * CC, bqkv + (size_t)l * 3 * CC,
            qkvb, BT, 3 * CC, CC);
        attn_kernel<<<grid_attn, 256>>>(qkvb, att);
        sgemm_kernel<1><<<grid_ffn1, 256>>>(
            att, W1a + (size_t)l * CC * FFF, b1a + (size_t)l * FFF,
            mid, BT, FFF, CC);
        sgemm_kernel<0><<<grid_ffn2, 256>>>(
            mid, W2a + (size_t)l * FFF * CC, b2a + (size_t)l * CC,
            tmp, BT, CC, FFF);
        ln_res_kernel<<<BT, 256>>>(tmp, g1 + (size_t)l * CC,
                                   beta1 + (size_t)l * CC, h);
        sgemm_kernel<1><<<grid_ffn1, 256>>>(
            h, W1b + (size_t)l * CC * FFF, b1b + (size_t)l * FFF,
            mid, BT, FFF, CC);
        sgemm_kernel<0><<<grid_ffn2, 256>>>(
            mid, W2b + (size_t)l * FFF * CC, b2b + (size_t)l * CC,
            tmp, BT, CC, FFF);
        ln_res_kernel<<<BT, 256>>>(tmp, g2 + (size_t)l * CC,
                                   beta2 + (size_t)l * CC, h);
    }

    sgemm_kernel<0><<<grid_lm, 256>>>(h, lmW, lmb, out, BT, VV, CC);
}

// round 3
// speedup vs baseline: 1.7374x; 1.7374x over previous
#include <cuda_runtime.h>
#include <cuda_bf16.h>
#include <math.h>
#include <stdint.h>

// ---------------------------------------------------------------------------
// Problem dimensions
// ---------------------------------------------------------------------------
#define LNUM 8
#define BB   8
#define TT   1024
#define CC   768
#define HH   12
#define DD   64
#define VV   1024
#define FFF  3072
#define BT   (BB*TT)   // 8192

// ---------------------------------------------------------------------------
// Scratch activations (fp32)
// ---------------------------------------------------------------------------
__device__ float g_h  [BT * CC];
__device__ float g_qkv[BT * 3 * CC];
__device__ float g_att[BT * CC];
__device__ float g_mid[BT * FFF];
__device__ float g_tmp[BT * CC];

// ---------------------------------------------------------------------------
// Pre-converted weights: transposed [N][K], bf16 hi/lo split
// ---------------------------------------------------------------------------
__device__ __nv_bfloat16 g_wqkv_h[LNUM * 3 * CC * CC];
__device__ __nv_bfloat16 g_wqkv_l[LNUM * 3 * CC * CC];
__device__ __nv_bfloat16 g_w1a_h [LNUM * CC * FFF];
__device__ __nv_bfloat16 g_w1a_l [LNUM * CC * FFF];
__device__ __nv_bfloat16 g_w2a_h [LNUM * CC * FFF];
__device__ __nv_bfloat16 g_w2a_l [LNUM * CC * FFF];
__device__ __nv_bfloat16 g_w1b_h [LNUM * CC * FFF];
__device__ __nv_bfloat16 g_w1b_l [LNUM * CC * FFF];
__device__ __nv_bfloat16 g_w2b_h [LNUM * CC * FFF];
__device__ __nv_bfloat16 g_w2b_l [LNUM * CC * FFF];
__device__ __nv_bfloat16 g_lm_h  [VV * CC];
__device__ __nv_bfloat16 g_lm_l  [VV * CC];

// ---------------------------------------------------------------------------
// Exact GELU
// ---------------------------------------------------------------------------
__device__ __forceinline__ float gelu_f(float x) {
    return 0.5f * x * (1.0f + erff(x * 0.70710678118654752f));
}

// ---------------------------------------------------------------------------
// HMMA m16n8k16 bf16 -> fp32
// ---------------------------------------------------------------------------
__device__ __forceinline__ void mma16816(float* c, const uint32_t* a,
                                         uint32_t b0, uint32_t b1) {
    asm volatile(
        "mma.sync.aligned.m16n8k16.row.col.f32.bf16.bf16.f32 "
        "{%0,%1,%2,%3}, {%4,%5,%6,%7}, {%8,%9}, {%0,%1,%2,%3};"
        : "+f"(c[0]), "+f"(c[1]), "+f"(c[2]), "+f"(c[3])
        : "r"(a[0]), "r"(a[1]), "r"(a[2]), "r"(a[3]), "r"(b0), "r"(b1));
}

// ---------------------------------------------------------------------------
// Weight pre-convert: W[K][N] fp32 -> Wt_hi[N][K], Wt_lo[N][K] bf16
// ---------------------------------------------------------------------------
__global__ void __launch_bounds__(256) convert_w_kernel(
    const float* __restrict__ W, __nv_bfloat16* __restrict__ hi,
    __nv_bfloat16* __restrict__ lo, int K, int N)
{
    __shared__ float t[32][33];
    const size_t loff = (size_t)blockIdx.z * K * N;
    const float* Wl = W + loff;
    __nv_bfloat16* hl = hi + loff;
    __nv_bfloat16* ll = lo + loff;
    const int kb = blockIdx.y << 5, nb = blockIdx.x << 5;
    const int tx = threadIdx.x, ty = threadIdx.y;
#pragma unroll
    for (int i = 0; i < 32; i += 8)
        t[ty + i][tx] = Wl[(size_t)(kb + ty + i) * N + nb + tx];
    __syncthreads();
#pragma unroll
    for (int i = 0; i < 32; i += 8) {
        float v = t[tx][ty + i];
        __nv_bfloat16 h = __float2bfloat16_rn(v);
        __nv_bfloat16 l = __float2bfloat16_rn(v - __bfloat162float(h));
        size_t o = (size_t)(nb + ty + i) * K + kb + tx;
        hl[o] = h; ll[o] = l;
    }
}

// ---------------------------------------------------------------------------
// HMMA GEMM: C[M,N] = epi(A[M,K]fp32 @ Bt[N,K]bf16(hi+lo) + bias)
// CTA 128x128, BK=32, 256 threads (8 warps, 4x2), warp tile 32x64.
// bf16x3 split: hi*hi + hi*lo + lo*hi. SMEM rows padded to 40 bf16 (80B).
// ---------------------------------------------------------------------------
#define RSTRIDE 40                     // bf16 elems per smem row (pad 32->40)
#define TILE_B  (128 * RSTRIDE * 2)    // 10240 bytes per matrix
#define STAGE_B (4 * TILE_B)           // Ah, Al, Bh, Bl
#define GSMEM_BYTES (2 * STAGE_B)      // 81920

template<int EPI>
__global__ void __launch_bounds__(256, 1) hgemm_kernel(
    const float* __restrict__ A, const __nv_bfloat16* __restrict__ Bh,
    const __nv_bfloat16* __restrict__ Bl, const float* __restrict__ bias,
    float* __restrict__ C, int N, int K)
{
    extern __shared__ __align__(16) char smem[];
    const int tid  = threadIdx.x;
    const int wid  = tid >> 5, lane = tid & 31;
    const int wm   = wid & 3,  wn   = wid >> 2;
    const int g    = lane >> 2, t   = lane & 3;
    const int bm   = blockIdx.y << 7, bn = blockIdx.x << 7;

    float acc[2][8][4];
#pragma unroll
    for (int mi = 0; mi < 2; mi++)
#pragma unroll
        for (int ni = 0; ni < 8; ni++)
#pragma unroll
            for (int r = 0; r < 4; r++) acc[mi][ni][r] = 0.f;

    // staging assignments
    const int ar  = (tid >> 3);            // with c offset: A row
    const int ac4 = (tid & 7) << 2;        // A col (float)
    const int br  = (tid >> 2);
    const int bc8 = (tid & 3) << 3;        // B col (bf16)

    const float* Ag = A + (size_t)(bm) * K;
    const __nv_bfloat16* Bgh = Bh + (size_t)bn * K;
    const __nv_bfloat16* Bgl = Bl + (size_t)bn * K;

    const int nk = K >> 5;

    float4 pa[4];
    uint4  pbh[2], pbl[2];
#pragma unroll
    for (int c = 0; c < 4; c++) {
        int idx = tid + (c << 8);
        pa[c] = *(const float4*)(Ag + (size_t)(idx >> 3) * K + ((idx & 7) << 2));
    }
#pragma unroll
    for (int c = 0; c < 2; c++) {
        int idx = tid + (c << 8);
        int row = idx >> 2, kc = (idx & 3) << 3;
        pbh[c] = *(const uint4*)(Bgh + (size_t)row * K + kc);
        pbl[c] = *(const uint4*)(Bgl + (size_t)row * K + kc);
    }

    for (int kt = 0; kt < nk; kt++) {
        char* st  = smem + (kt & 1) * STAGE_B;
        char* Ahp = st;
        char* Alp = st + TILE_B;
        char* Bhp = st + 2 * TILE_B;
        char* Blp = st + 3 * TILE_B;

        // store A hi/lo (fp32 -> bf16 split)
#pragma unroll
        for (int c = 0; c < 4; c++) {
            int idx = tid + (c << 8);
            int row = idx >> 3, col = (idx & 7) << 2;
            float4 v = pa[c];
            __nv_bfloat16 h0 = __float2bfloat16_rn(v.x);
            __nv_bfloat16 h1 = __float2bfloat16_rn(v.y);
            __nv_bfloat16 h2 = __float2bfloat16_rn(v.z);
            __nv_bfloat16 h3 = __float2bfloat16_rn(v.w);
            __nv_bfloat16 l0 = __float2bfloat16_rn(v.x - __bfloat162float(h0));
            __nv_bfloat16 l1 = __float2bfloat16_rn(v.y - __bfloat162float(h1));
            __nv_bfloat16 l2 = __float2bfloat16_rn(v.z - __bfloat162float(h2));
            __nv_bfloat16 l3 = __float2bfloat16_rn(v.w - __bfloat162float(h3));
            __nv_bfloat162 ph0 = __halves2bfloat162(h0, h1);
            __nv_bfloat162 ph1 = __halves2bfloat162(h2, h3);
            __nv_bfloat162 pl0 = __halves2bfloat162(l0, l1);
            __nv_bfloat162 pl1 = __halves2bfloat162(l2, l3);
            uint2 uh = make_uint2(*(uint32_t*)&ph0, *(uint32_t*)&ph1);
            uint2 ul = make_uint2(*(uint32_t*)&pl0, *(uint32_t*)&pl1);
            int off = row * (RSTRIDE * 2) + col * 2;
            *(uint2*)(Ahp + off) = uh;
            *(uint2*)(Alp + off) = ul;
        }
        // store B hi/lo (already bf16)
#pragma unroll
        for (int c = 0; c < 2; c++) {
            int idx = tid + (c << 8);
            int row = idx >> 2, kc = (idx & 3) << 3;
            int off = row * (RSTRIDE * 2) + kc * 2;
            *(uint4*)(Bhp + off) = pbh[c];
            *(uint4*)(Blp + off) = pbl[c];
        }
        __syncthreads();

        // prefetch next k-tile
        if (kt + 1 < nk) {
            const float* Agn = Ag + (kt + 1) * 32;
            const __nv_bfloat16* Bghn = Bgh + (kt + 1) * 32;
            const __nv_bfloat16* Bgln = Bgl + (kt + 1) * 32;
#pragma unroll
            for (int c = 0; c < 4; c++) {
                int idx = tid + (c << 8);
                pa[c] = *(const float4*)(Agn + (size_t)(idx >> 3) * K + ((idx & 7) << 2));
            }
#pragma unroll
            for (int c = 0; c < 2; c++) {
                int idx = tid + (c << 8);
                int row = idx >> 2, kc = (idx & 3) << 3;
                pbh[c] = *(const uint4*)(Bghn + (size_t)row * K + kc);
                pbl[c] = *(const uint4*)(Bgln + (size_t)row * K + kc);
            }
        }

        // compute: 2 k16-steps
#pragma unroll
        for (int ks = 0; ks < 2; ks++) {
            uint32_t ah[2][4], al[2][4];
#pragma unroll
            for (int mi = 0; mi < 2; mi++) {
                int rb = wm * 32 + mi * 16 + g;
                int base = rb * (RSTRIDE * 2) + ks * 32 + t * 4;
                ah[mi][0] = *(const uint32_t*)(Ahp + base);
                ah[mi][1] = *(const uint32_t*)(Ahp + base + 8 * (RSTRIDE * 2));
                ah[mi][2] = *(const uint32_t*)(Ahp + base + 16);
                ah[mi][3] = *(const uint32_t*)(Ahp + base + 8 * (RSTRIDE * 2) + 16);
                al[mi][0] = *(const uint32_t*)(Alp + base);
                al[mi][1] = *(const uint32_t*)(Alp + base + 8 * (RSTRIDE * 2));
                al[mi][2] = *(const uint32_t*)(Alp + base + 16);
                al[mi][3] = *(const uint32_t*)(Alp + base + 8 * (RSTRIDE * 2) + 16);
            }
#pragma unroll
            for (int ni = 0; ni < 8; ni++) {
                int nb0 = wn * 64 + ni * 8 + g;
                int base = nb0 * (RSTRIDE * 2) + ks * 32 + t * 4;
                uint32_t bh0 = *(const uint32_t*)(Bhp + base);
                uint32_t bh1 = *(const uint32_t*)(Bhp + base + 16);
                uint32_t bl0 = *(const uint32_t*)(Blp + base);
                uint32_t bl1 = *(const uint32_t*)(Blp + base + 16);
#pragma unroll
                for (int mi = 0; mi < 2; mi++) {
                    mma16816(acc[mi][ni], ah[mi], bh0, bh1);
                    mma16816(acc[mi][ni], ah[mi], bl0, bl1);
                    mma16816(acc[mi][ni], al[mi], bh0, bh1);
                }
            }
        }
        __syncthreads();
    }

    // epilogue
#pragma unroll
    for (int ni = 0; ni < 8; ni++) {
        int col = bn + wn * 64 + ni * 8 + t * 2;
        float b0 = bias[col], b1 = bias[col + 1];
#pragma unroll
        for (int mi = 0; mi < 2; mi++) {
            int r0 = bm + wm * 32 + mi * 16 + g;
            float v0 = acc[mi][ni][0] + b0;
            float v1 = acc[mi][ni][1] + b1;
            float v2 = acc[mi][ni][2] + b0;
            float v3 = acc[mi][ni][3] + b1;
            if (EPI == 1) {
                v0 = gelu_f(v0); v1 = gelu_f(v1);
                v2 = gelu_f(v2); v3 = gelu_f(v3);
            }
            *(float2*)(C + (size_t)r0 * N + col)       = make_float2(v0, v1);
            *(float2*)(C + (size_t)(r0 + 8) * N + col) = make_float2(v2, v3);
        }
    }
}

// ---------------------------------------------------------------------------
// Embedding
// ---------------------------------------------------------------------------
__global__ void __launch_bounds__(192) embed_kernel(
    const int* __restrict__ x, const float* __restrict__ emb,
    const float* __restrict__ pos, float* __restrict__ h)
{
    const int bt  = blockIdx.x;
    const int tok = x[bt];
    const int t   = bt & (TT - 1);
    const float4* e4 = (const float4*)(emb + (size_t)tok * CC);
    const float4* p4 = (const float4*)(pos + (size_t)t   * CC);
    float4*       h4 = (float4*)(h + (size_t)bt * CC);
    const int i = threadIdx.x;
    float4 a = e4[i], b = p4[i];
    h4[i] = make_float4(a.x + b.x, a.y + b.y, a.z + b.z, a.w + b.w);
}

// ---------------------------------------------------------------------------
// Fused causal flash attention (fp32 SIMT)
// ---------------------------------------------------------------------------
__global__ void __launch_bounds__(256) attn_kernel(
    const float* __restrict__ qkv, float* __restrict__ out)
{
    __shared__ float Qt[64][64];
    __shared__ float KP[64][64];
    __shared__ float Vs[64][64];

    const int tid   = threadIdx.x;
    const int qtile = blockIdx.x;
    const int bh    = blockIdx.y;
    const int b     = bh / HH;
    const int h     = bh % HH;
    const int qb    = qtile << 6;
    const float* base = qkv + (size_t)b * TT * 3 * CC;

    const int cc   = tid & 63;
    const int dblk = tid >> 6;

    {
        const float* Qg = base + (size_t)(qb + cc) * 3 * CC + CC + h * DD;
#pragma unroll
        for (int i = 0; i < 4; i++) {
            int d0 = (dblk + (i << 2)) << 2;
            float4 g = *(const float4*)(Qg + d0);
            Qt[d0 + 0][cc] = g.x; Qt[d0 + 1][cc] = g.y;
            Qt[d0 + 2][cc] = g.z; Qt[d0 + 3][cc] = g.w;
        }
    }

    const int tx = tid & 15, ty = tid >> 4;
    float m[4], l[4], O[4][4];
#pragma unroll
    for (int i = 0; i < 4; i++) {
        m[i] = -1e30f; l[i] = 0.f;
#pragma unroll
        for (int j = 0; j < 4; j++) O[i][j] = 0.f;
    }

    for (int kt = 0; kt <= qtile; kt++) {
        const int kb = kt << 6;
        __syncthreads();
        {
            const float* Kg = base + (size_t)(kb + cc) * 3 * CC + h * DD;
#pragma unroll
            for (int i = 0; i < 4; i++) {
                int d0 = (dblk + (i << 2)) << 2;
                float4 g = *(const float4*)(Kg + d0);
                KP[d0 + 0][cc] = g.x; KP[d0 + 1][cc] = g.y;
                KP[d0 + 2][cc] = g.z; KP[d0 + 3][cc] = g.w;
            }
        }
#pragma unroll
        for (int i = 0; i < 4; i++) {
            int f  = tid + (i << 8);
            int vc = f >> 4;
            int vd = (f & 15) << 2;
            float4 g = *(const float4*)(base + (size_t)(kb + vc) * 3 * CC
                                        + 2 * CC + h * DD + vd);
            *(float4*)&Vs[vc][vd] = g;
        }
        __syncthreads();

        float S[4][4];
#pragma unroll
        for (int i = 0; i < 4; i++)
#pragma unroll
            for (int j = 0; j < 4; j++) S[i][j] = 0.f;
#pragma unroll 8
        for (int d = 0; d < 64; d++) {
            float4 a  = *(const float4*)&Qt[d][(ty << 2)];
            float4 bq = *(const float4*)&KP[d][(tx << 2)];
            float av[4] = {a.x, a.y, a.z, a.w};
            float bv[4] = {bq.x, bq.y, bq.z, bq.w};
#pragma unroll
            for (int i = 0; i < 4; i++)
#pragma unroll
                for (int j = 0; j < 4; j++)
                    S[i][j] = fmaf(av[i], bv[j], S[i][j]);
        }
        const float scale = 0.125f;
        if (kt == qtile) {
#pragma unroll
            for (int i = 0; i < 4; i++) {
                int q = qb + (ty << 2) + i;
#pragma unroll
                for (int j = 0; j < 4; j++) {
                    int kk = kb + (tx << 2) + j;
                    S[i][j] = (kk <= q) ? S[i][j] * scale : -1e30f;
                }
            }
        } else {
#pragma unroll
            for (int i = 0; i < 4; i++)
#pragma unroll
                for (int j = 0; j < 4; j++) S[i][j] *= scale;
        }

        float alpha[4];
#pragma unroll
        for (int i = 0; i < 4; i++) {
            float pm = fmaxf(fmaxf(S[i][0], S[i][1]), fmaxf(S[i][2], S[i][3]));
#pragma unroll
            for (int o = 1; o < 16; o <<= 1)
                pm = fmaxf(pm, __shfl_xor_sync(0xffffffffu, pm, o));
            float mn = fmaxf(m[i], pm);
            alpha[i] = __expf(m[i] - mn);
            float rs = 0.f;
#pragma unroll
            for (int j = 0; j < 4; j++) { S[i][j] = __expf(S[i][j] - mn); rs += S[i][j]; }
#pragma unroll
            for (int o = 1; o < 16; o <<= 1)
                rs += __shfl_xor_sync(0xffffffffu, rs, o);
            l[i] = l[i] * alpha[i] + rs;
            m[i] = mn;
#pragma unroll
            for (int j = 0; j < 4; j++) O[i][j] *= alpha[i];
        }

        __syncthreads();
#pragma unroll
        for (int i = 0; i < 4; i++)
            *(float4*)&KP[(ty << 2) + i][(tx << 2)] =
                make_float4(S[i][0], S[i][1], S[i][2], S[i][3]);
        __syncthreads();

#pragma unroll 4
        for (int c = 0; c < 64; c++) {
            float4 v = *(const float4*)&Vs[c][(tx << 2)];
            float vv[4] = {v.x, v.y, v.z, v.w};
#pragma unroll
            for (int i = 0; i < 4; i++) {
                float p = KP[(ty << 2) + i][c];
#pragma unroll
                for (int j = 0; j < 4; j++)
                    O[i][j] = fmaf(p, vv[j], O[i][j]);
            }
        }
    }

#pragma unroll
    for (int i = 0; i < 4; i++) {
        float inv = 1.0f / l[i];
        float* op = out + ((size_t)b * TT + qb + (ty << 2) + i) * CC
                        + h * DD + (tx << 2);
        *(float4*)op = make_float4(O[i][0] * inv, O[i][1] * inv,
                                   O[i][2] * inv, O[i][3] * inv);
    }
}

// ---------------------------------------------------------------------------
// Fused LayerNorm + residual add
// ---------------------------------------------------------------------------
__global__ void __launch_bounds__(256) ln_res_kernel(
    const float* __restrict__ y, const float* __restrict__ g,
    const float* __restrict__ be, float* __restrict__ h)
{
    __shared__ float red1[8];
    __shared__ float red2[8];
    const int row = blockIdx.x;
    const int tid = threadIdx.x;
    const float* yr = y + (size_t)row * CC;

    float v0 = yr[tid], v1 = yr[tid + 256], v2 = yr[tid + 512];
    float s = v0 + v1 + v2;
#pragma unroll
    for (int o = 16; o; o >>= 1) s += __shfl_xor_sync(0xffffffffu, s, o);
    if ((tid & 31) == 0) red1[tid >> 5] = s;
    __syncthreads();
    float tot = 0.f;
#pragma unroll
    for (int i = 0; i < 8; i++) tot += red1[i];
    float mu = tot * (1.0f / 768.0f);

    float d0 = v0 - mu, d1 = v1 - mu, d2 = v2 - mu;
    float q = d0 * d0 + d1 * d1 + d2 * d2;
#pragma unroll
    for (int o = 16; o; o >>= 1) q += __shfl_xor_sync(0xffffffffu, q, o);
    if ((tid & 31) == 0) red2[tid >> 5] = q;
    __syncthreads();
    float qt = 0.f;
#pragma unroll
    for (int i = 0; i < 8; i++) qt += red2[i];
    float rstd = rsqrtf(qt * (1.0f / 768.0f) + 1e-5f);

    float* hr = h + (size_t)row * CC;
    hr[tid]       += d0 * rstd * g[tid]       + be[tid];
    hr[tid + 256] += d1 * rstd * g[tid + 256] + be[tid + 256];
    hr[tid + 512] += d2 * rstd * g[tid + 512] + be[tid + 512];
}

// ---------------------------------------------------------------------------
// Launch
// ---------------------------------------------------------------------------
extern "C" void kernel_launch(void* const* d_in, const int* in_sizes, int n_in,
                              void* d_out, int out_size)
{
    const int*   x     = (const int*)  d_in[0];
    const float* embed = (const float*)d_in[1];
    const float* pos   = (const float*)d_in[2];
    const float* Wqkv  = (const float*)d_in[3];
    const float* bqkv  = (const float*)d_in[4];
    const float* W1a   = (const float*)d_in[5];
    const float* b1a   = (const float*)d_in[6];
    const float* W2a   = (const float*)d_in[7];
    const float* b2a   = (const float*)d_in[8];
    const float* g1    = (const float*)d_in[9];
    const float* beta1 = (const float*)d_in[10];
    const float* W1b   = (const float*)d_in[11];
    const float* b1b   = (const float*)d_in[12];
    const float* W2b   = (const float*)d_in[13];
    const float* b2b   = (const float*)d_in[14];
    const float* g2    = (const float*)d_in[15];
    const float* beta2 = (const float*)d_in[16];
    const float* lmW   = (const float*)d_in[17];
    const float* lmb   = (const float*)d_in[18];
    float* out = (float*)d_out;

    float *h, *qkvb, *att, *mid, *tmp;
    cudaGetSymbolAddress((void**)&h,    g_h);
    cudaGetSymbolAddress((void**)&qkvb, g_qkv);
    cudaGetSymbolAddress((void**)&att,  g_att);
    cudaGetSymbolAddress((void**)&mid,  g_mid);
    cudaGetSymbolAddress((void**)&tmp,  g_tmp);

    __nv_bfloat16 *wqh, *wql, *w1ah, *w1al, *w2ah, *w2al,
                  *w1bh, *w1bl, *w2bh, *w2bl, *lmh, *lml;
    cudaGetSymbolAddress((void**)&wqh,  g_wqkv_h);
    cudaGetSymbolAddress((void**)&wql,  g_wqkv_l);
    cudaGetSymbolAddress((void**)&w1ah, g_w1a_h);
    cudaGetSymbolAddress((void**)&w1al, g_w1a_l);
    cudaGetSymbolAddress((void**)&w2ah, g_w2a_h);
    cudaGetSymbolAddress((void**)&w2al, g_w2a_l);
    cudaGetSymbolAddress((void**)&w1bh, g_w1b_h);
    cudaGetSymbolAddress((void**)&w1bl, g_w1b_l);
    cudaGetSymbolAddress((void**)&w2bh, g_w2b_h);
    cudaGetSymbolAddress((void**)&w2bl, g_w2b_l);
    cudaGetSymbolAddress((void**)&lmh,  g_lm_h);
    cudaGetSymbolAddress((void**)&lml,  g_lm_l);

    cudaFuncSetAttribute(hgemm_kernel<0>,
        cudaFuncAttributeMaxDynamicSharedMemorySize, GSMEM_BYTES);
    cudaFuncSetAttribute(hgemm_kernel<1>,
        cudaFuncAttributeMaxDynamicSharedMemorySize, GSMEM_BYTES);

    // ---- weight pre-convert (transpose + bf16 hi/lo split) ----
    const dim3 cb(32, 8);
    convert_w_kernel<<<dim3(3 * CC / 32, CC / 32, LNUM), cb>>>(Wqkv, wqh, wql, CC, 3 * CC);
    convert_w_kernel<<<dim3(FFF / 32, CC / 32, LNUM), cb>>>(W1a, w1ah, w1al, CC, FFF);
    convert_w_kernel<<<dim3(CC / 32, FFF / 32, LNUM), cb>>>(W2a, w2ah, w2al, FFF, CC);
    convert_w_kernel<<<dim3(FFF / 32, CC / 32, LNUM), cb>>>(W1b, w1bh, w1bl, CC, FFF);
    convert_w_kernel<<<dim3(CC / 32, FFF / 32, LNUM), cb>>>(W2b, w2bh, w2bl, FFF, CC);
    convert_w_kernel<<<dim3(VV / 32, CC / 32, 1),     cb>>>(lmW, lmh, lml, CC, VV);

    embed_kernel<<<BT, 192>>>(x, embed, pos, h);

    const dim3 grid_qkv (3 * CC / 128, BT / 128);
    const dim3 grid_ffn1(FFF / 128,    BT / 128);
    const dim3 grid_ffn2(CC / 128,     BT / 128);
    const dim3 grid_lm  (VV / 128,     BT / 128);
    const dim3 grid_attn(TT / 64, BB * HH);

    for (int l = 0; l < LNUM; l++) {
        hgemm_kernel<0><<<grid_qkv, 256, GSMEM_BYTES>>>(
            h, wqh + (size_t)l * 3 * CC * CC, wql + (size_t)l * 3 * CC * CC,
            bqkv + (size_t)l * 3 * CC, qkvb, 3 * CC, CC);
        attn_kernel<<<grid_attn, 256>>>(qkvb, att);
        hgemm_kernel<1><<<grid_ffn1, 256, GSMEM_BYTES>>>(
            att, w1ah + (size_t)l * CC * FFF, w1al + (size_t)l * CC * FFF,
            b1a + (size_t)l * FFF, mid, FFF, CC);
        hgemm_kernel<0><<<grid_ffn2, 256, GSMEM_BYTES>>>(
            mid, w2ah + (size_t)l * CC * FFF, w2al + (size_t)l * CC * FFF,
            b2a + (size_t)l * CC, tmp, CC, FFF);
        ln_res_kernel<<<BT, 256>>>(tmp, g1 + (size_t)l * CC,
                                   beta1 + (size_t)l * CC, h);
        hgemm_kernel<1><<<grid_ffn1, 256, GSMEM_BYTES>>>(
            h, w1bh + (size_t)l * CC * FFF, w1bl + (size_t)l * CC * FFF,
            b1b + (size_t)l * FFF, mid, FFF, CC);
        hgemm_kernel<0><<<grid_ffn2, 256, GSMEM_BYTES>>>(
            mid, w2bh + (size_t)l * CC * FFF, w2bl + (size_t)l * CC * FFF,
            b2b + (size_t)l * CC, tmp, CC, FFF);
        ln_res_kernel<<<BT, 256>>>(tmp, g2 + (size_t)l * CC,
                                   beta2 + (size_t)l * CC, h);
    }

    hgemm_kernel<0><<<grid_lm, 256, GSMEM_BYTES>>>(
        h, lmh, lml, lmb, out, VV, CC);
}

// round 4
// speedup vs baseline: 1.9254x; 1.1082x over previous
#include <cuda_runtime.h>
#include <cuda_bf16.h>
#include <math.h>
#include <stdint.h>

#define LNUM 8
#define BB   8
#define TT   1024
#define CC   768
#define HH   12
#define DD   64
#define VV   1024
#define FFF  3072
#define BT   (BB*TT)   // 8192

// ---------------------------------------------------------------------------
// Scratch activations
// ---------------------------------------------------------------------------
__device__ float g_h  [BT * CC];          // residual stream fp32
__device__ float g_qkv[BT * 3 * CC];      // qkv fp32 (attn input)
__device__ float g_tmp[BT * CC];          // FFN2 out fp32 (LN input)
__device__ __nv_bfloat16 g_hh [BT * CC];  // h hi/lo (GEMM A)
__device__ __nv_bfloat16 g_hl [BT * CC];
__device__ __nv_bfloat16 g_ath[BT * CC];  // attn out hi/lo
__device__ __nv_bfloat16 g_atl[BT * CC];
__device__ __nv_bfloat16 g_mih[BT * FFF]; // FFN mid hi/lo
__device__ __nv_bfloat16 g_mil[BT * FFF];

// ---------------------------------------------------------------------------
// Pre-converted weights: transposed [N][K], bf16 hi/lo split
// ---------------------------------------------------------------------------
__device__ __nv_bfloat16 g_wqkv_h[LNUM * 3 * CC * CC];
__device__ __nv_bfloat16 g_wqkv_l[LNUM * 3 * CC * CC];
__device__ __nv_bfloat16 g_w1a_h [LNUM * CC * FFF];
__device__ __nv_bfloat16 g_w1a_l [LNUM * CC * FFF];
__device__ __nv_bfloat16 g_w2a_h [LNUM * CC * FFF];
__device__ __nv_bfloat16 g_w2a_l [LNUM * CC * FFF];
__device__ __nv_bfloat16 g_w1b_h [LNUM * CC * FFF];
__device__ __nv_bfloat16 g_w1b_l [LNUM * CC * FFF];
__device__ __nv_bfloat16 g_w2b_h [LNUM * CC * FFF];
__device__ __nv_bfloat16 g_w2b_l [LNUM * CC * FFF];
__device__ __nv_bfloat16 g_lm_h  [VV * CC];
__device__ __nv_bfloat16 g_lm_l  [VV * CC];

// ---------------------------------------------------------------------------
// Helpers
// ---------------------------------------------------------------------------
__device__ __forceinline__ float gelu_f(float x) {
    return 0.5f * x * (1.0f + erff(x * 0.70710678118654752f));
}

__device__ __forceinline__ uint32_t smem_u32(const void* p) {
    uint32_t a;
    asm("{ .reg .u64 t; cvta.to.shared.u64 t, %1; cvt.u32.u64 %0, t; }"
        : "=r"(a) : "l"(p));
    return a;
}

__device__ __forceinline__ void cpa16(uint32_t s, const void* g) {
    asm volatile("cp.async.cg.shared.global [%0], [%1], 16;"
                 :: "r"(s), "l"(g));
}
#define CP_COMMIT() asm volatile("cp.async.commit_group;" ::: "memory")
#define CP_WAIT1()  asm volatile("cp.async.wait_group 1;" ::: "memory")
#define CP_WAIT0()  asm volatile("cp.async.wait_group 0;" ::: "memory")

__device__ __forceinline__ void ldsm4(uint32_t* r, uint32_t a) {
    asm volatile("ldmatrix.sync.aligned.m8n8.x4.shared.b16 {%0,%1,%2,%3}, [%4];"
        : "=r"(r[0]), "=r"(r[1]), "=r"(r[2]), "=r"(r[3]) : "r"(a));
}

__device__ __forceinline__ void mma16816(float* c, const uint32_t* a,
                                         uint32_t b0, uint32_t b1) {
    asm volatile(
        "mma.sync.aligned.m16n8k16.row.col.f32.bf16.bf16.f32 "
        "{%0,%1,%2,%3}, {%4,%5,%6,%7}, {%8,%9}, {%0,%1,%2,%3};"
        : "+f"(c[0]), "+f"(c[1]), "+f"(c[2]), "+f"(c[3])
        : "r"(a[0]), "r"(a[1]), "r"(a[2]), "r"(a[3]), "r"(b0), "r"(b1));
}

__device__ __forceinline__ uint32_t pack_bf2(float a, float b) {
    __nv_bfloat162 p = __floats2bfloat162_rn(a, b);
    return *reinterpret_cast<uint32_t*>(&p);
}
// split v into hi/lo bf16 pair packs
__device__ __forceinline__ void split2(float v0, float v1,
                                       uint32_t& hp, uint32_t& lp) {
    __nv_bfloat16 h0 = __float2bfloat16_rn(v0);
    __nv_bfloat16 h1 = __float2bfloat16_rn(v1);
    float l0 = v0 - __bfloat162float(h0);
    float l1 = v1 - __bfloat162float(h1);
    __nv_bfloat162 hh = __halves2bfloat162(h0, h1);
    hp = *reinterpret_cast<uint32_t*>(&hh);
    lp = pack_bf2(l0, l1);
}

// ---------------------------------------------------------------------------
// Weight pre-convert: W[K][N] fp32 -> Wt_hi[N][K], Wt_lo[N][K] bf16
// ---------------------------------------------------------------------------
__global__ void __launch_bounds__(256) convert_w_kernel(
    const float* __restrict__ W, __nv_bfloat16* __restrict__ hi,
    __nv_bfloat16* __restrict__ lo, int K, int N)
{
    __shared__ float t[32][33];
    const size_t loff = (size_t)blockIdx.z * K * N;
    const float* Wl = W + loff;
    __nv_bfloat16* hl = hi + loff;
    __nv_bfloat16* ll = lo + loff;
    const int kb = blockIdx.y << 5, nb = blockIdx.x << 5;
    const int tx = threadIdx.x, ty = threadIdx.y;
#pragma unroll
    for (int i = 0; i < 32; i += 8)
        t[ty + i][tx] = Wl[(size_t)(kb + ty + i) * N + nb + tx];
    __syncthreads();
#pragma unroll
    for (int i = 0; i < 32; i += 8) {
        float v = t[tx][ty + i];
        __nv_bfloat16 h = __float2bfloat16_rn(v);
        __nv_bfloat16 l = __float2bfloat16_rn(v - __bfloat162float(h));
        size_t o = (size_t)(nb + ty + i) * K + kb + tx;
        hl[o] = h; ll[o] = l;
    }
}

// ---------------------------------------------------------------------------
// HMMA GEMM v2: C = epi(A(hi+lo) @ Bt(hi+lo) + bias)
// A: [M][K] bf16 hi/lo, B: [N][K] bf16 hi/lo, all pre-split.
// CTA 128x128, BK=32, 8 warps (4x2), warp tile 32x64.
// cp.async 2-stage pipeline, ldmatrix fragments, padded 80B smem rows.
// WF32: write fp32 C. WHL: write bf16 hi/lo C (Ch/Cl).
// ---------------------------------------------------------------------------
#define RSB   80                       // bytes per smem row (32 bf16 + pad)
#define TILEB (128 * RSB)              // 10240
#define STAGEB (4 * TILEB)             // 40960: Ah | Al | Bh | Bl
#define GSMEM_BYTES (2 * STAGEB)       // 81920

template<int EPI, int WF32, int WHL>
__global__ void __launch_bounds__(256, 2) hgemm_kernel(
    const __nv_bfloat16* __restrict__ Ah, const __nv_bfloat16* __restrict__ Al,
    const __nv_bfloat16* __restrict__ Bh, const __nv_bfloat16* __restrict__ Bl,
    const float* __restrict__ bias, float* __restrict__ C,
    __nv_bfloat16* __restrict__ Ch, __nv_bfloat16* __restrict__ Cl,
    int N, int K)
{
    extern __shared__ __align__(128) char smem[];
    const int tid  = threadIdx.x;
    const int lane = tid & 31;
    const int wid  = tid >> 5;
    const int wm   = wid & 3, wn = wid >> 2;
    const int g    = lane >> 2, t = lane & 3;
    const int bm   = blockIdx.y << 7, bn = blockIdx.x << 7;
    const uint32_t sbase = smem_u32(smem);

    const __nv_bfloat16* gp[4];
    gp[0] = Ah + (size_t)bm * K;
    gp[1] = Al + (size_t)bm * K;
    gp[2] = Bh + (size_t)bn * K;
    gp[3] = Bl + (size_t)bn * K;

    const int srow = tid >> 2;          // staging row 0..127 (i=0), +64 rows? no:
    const int sc   = tid & 3;           // chunk 0..3

    float acc[2][8][4];
#pragma unroll
    for (int mi = 0; mi < 2; mi++)
#pragma unroll
        for (int ni = 0; ni < 8; ni++)
#pragma unroll
            for (int r = 0; r < 4; r++) acc[mi][ni][r] = 0.f;

    const int nk = K >> 5;

#define STAGE(kt, buf) do {                                                   \
    uint32_t s0 = sbase + (buf) * STAGEB;                                     \
    _Pragma("unroll")                                                         \
    for (int m = 0; m < 4; m++) {                                             \
        _Pragma("unroll")                                                     \
        for (int i = 0; i < 2; i++) {                                         \
            int q = tid + (i << 8);                                           \
            int row = q >> 2, c = q & 3;                                      \
            cpa16(s0 + m * TILEB + row * RSB + c * 16,                        \
                  gp[m] + (size_t)row * K + (kt) * 32 + c * 8);               \
        }                                                                     \
    }                                                                         \
    CP_COMMIT();                                                              \
} while (0)

    STAGE(0, 0);
    STAGE(1, 1);

    // fragment lane addressing (byte offsets within tile)
    const int arow = wm * 32 + (lane & 15);          // + mi*16
    const int akh  = (lane >> 4) & 1;                // k half
    const int brow = wn * 64 + (lane & 7) + (((lane >> 4) & 1) << 3); // + nip*16
    const int bkh  = (lane >> 3) & 1;

    for (int kt = 0; kt < nk; kt++) {
        if (kt + 1 < nk) CP_WAIT1(); else CP_WAIT0();
        __syncthreads();

        const uint32_t st = sbase + (kt & 1) * STAGEB;
        const uint32_t Ahp = st, Alp = st + TILEB;
        const uint32_t Bhp = st + 2 * TILEB, Blp = st + 3 * TILEB;

#pragma unroll
        for (int ks = 0; ks < 2; ks++) {
            const int ko = ks * 32;
            uint32_t ah[2][4], al[2][4];
#pragma unroll
            for (int mi = 0; mi < 2; mi++) {
                uint32_t ao = (uint32_t)((arow + mi * 16) * RSB + ko + akh * 16);
                ldsm4(ah[mi], Ahp + ao);
                ldsm4(al[mi], Alp + ao);
            }
#pragma unroll
            for (int nip = 0; nip < 4; nip++) {
                uint32_t bo = (uint32_t)((brow + nip * 16) * RSB + ko + bkh * 16);
                uint32_t bh[4], bl[4];
                ldsm4(bh, Bhp + bo);
                ldsm4(bl, Blp + bo);
#pragma unroll
                for (int mi = 0; mi < 2; mi++) {
                    mma16816(acc[mi][2 * nip],     ah[mi], bh[0], bh[1]);
                    mma16816(acc[mi][2 * nip],     ah[mi], bl[0], bl[1]);
                    mma16816(acc[mi][2 * nip],     al[mi], bh[0], bh[1]);
                    mma16816(acc[mi][2 * nip + 1], ah[mi], bh[2], bh[3]);
                    mma16816(acc[mi][2 * nip + 1], ah[mi], bl[2], bl[3]);
                    mma16816(acc[mi][2 * nip + 1], al[mi], bh[2], bh[3]);
                }
            }
        }
        __syncthreads();
        if (kt + 2 < nk) STAGE(kt + 2, kt & 1);
    }
#undef STAGE

    // epilogue
#pragma unroll
    for (int ni = 0; ni < 8; ni++) {
        int col = bn + wn * 64 + ni * 8 + t * 2;
        float b0 = bias[col], b1 = bias[col + 1];
#pragma unroll
        for (int mi = 0; mi < 2; mi++) {
            int r0 = bm + wm * 32 + mi * 16 + g;
            float v0 = acc[mi][ni][0] + b0;
            float v1 = acc[mi][ni][1] + b1;
            float v2 = acc[mi][ni][2] + b0;
            float v3 = acc[mi][ni][3] + b1;
            if (EPI == 1) {
                v0 = gelu_f(v0); v1 = gelu_f(v1);
                v2 = gelu_f(v2); v3 = gelu_f(v3);
            }
            size_t o0 = (size_t)r0 * N + col;
            size_t o1 = (size_t)(r0 + 8) * N + col;
            if (WF32) {
                *(float2*)(C + o0) = make_float2(v0, v1);
                *(float2*)(C + o1) = make_float2(v2, v3);
            }
            if (WHL) {
                uint32_t hp, lp;
                split2(v0, v1, hp, lp);
                *(uint32_t*)(Ch + o0) = hp;
                *(uint32_t*)(Cl + o0) = lp;
                split2(v2, v3, hp, lp);
                *(uint32_t*)(Ch + o1) = hp;
                *(uint32_t*)(Cl + o1) = lp;
            }
        }
    }
}

// ---------------------------------------------------------------------------
// Embedding: h = embed[x] + pos ; writes fp32 + hi/lo
// ---------------------------------------------------------------------------
__global__ void __launch_bounds__(192) embed_kernel(
    const int* __restrict__ x, const float* __restrict__ emb,
    const float* __restrict__ pos, float* __restrict__ h,
    __nv_bfloat16* __restrict__ hh, __nv_bfloat16* __restrict__ hl)
{
    const int bt  = blockIdx.x;
    const int tok = x[bt];
    const int t   = bt & (TT - 1);
    const float4* e4 = (const float4*)(emb + (size_t)tok * CC);
    const float4* p4 = (const float4*)(pos + (size_t)t   * CC);
    const int i = threadIdx.x;
    float4 a = e4[i], b = p4[i];
    float4 s = make_float4(a.x + b.x, a.y + b.y, a.z + b.z, a.w + b.w);
    ((float4*)(h + (size_t)bt * CC))[i] = s;
    size_t o = (size_t)bt * CC + i * 4;
    uint32_t hp, lp;
    split2(s.x, s.y, hp, lp);
    *(uint32_t*)(hh + o) = hp;     *(uint32_t*)(hl + o) = lp;
    split2(s.z, s.w, hp, lp);
    *(uint32_t*)(hh + o + 2) = hp; *(uint32_t*)(hl + o + 2) = lp;
}

// ---------------------------------------------------------------------------
// Fused causal flash attention (fp32 SIMT) -> bf16 hi/lo output
// ---------------------------------------------------------------------------
__global__ void __launch_bounds__(256) attn_kernel(
    const float* __restrict__ qkv,
    __nv_bfloat16* __restrict__ outh, __nv_bfloat16* __restrict__ outl)
{
    __shared__ float Qt[64][64];
    __shared__ float KP[64][64];
    __shared__ float Vs[64][64];

    const int tid   = threadIdx.x;
    const int qtile = blockIdx.x;
    const int bh    = blockIdx.y;
    const int b     = bh / HH;
    const int h     = bh % HH;
    const int qb    = qtile << 6;
    const float* base = qkv + (size_t)b * TT * 3 * CC;

    const int cc   = tid & 63;
    const int dblk = tid >> 6;

    {
        const float* Qg = base + (size_t)(qb + cc) * 3 * CC + CC + h * DD;
#pragma unroll
        for (int i = 0; i < 4; i++) {
            int d0 = (dblk + (i << 2)) << 2;
            float4 g = *(const float4*)(Qg + d0);
            Qt[d0 + 0][cc] = g.x; Qt[d0 + 1][cc] = g.y;
            Qt[d0 + 2][cc] = g.z; Qt[d0 + 3][cc] = g.w;
        }
    }

    const int tx = tid & 15, ty = tid >> 4;
    float m[4], l[4], O[4][4];
#pragma unroll
    for (int i = 0; i < 4; i++) {
        m[i] = -1e30f; l[i] = 0.f;
#pragma unroll
        for (int j = 0; j < 4; j++) O[i][j] = 0.f;
    }

    for (int kt = 0; kt <= qtile; kt++) {
        const int kb = kt << 6;
        __syncthreads();
        {
            const float* Kg = base + (size_t)(kb + cc) * 3 * CC + h * DD;
#pragma unroll
            for (int i = 0; i < 4; i++) {
                int d0 = (dblk + (i << 2)) << 2;
                float4 g = *(const float4*)(Kg + d0);
                KP[d0 + 0][cc] = g.x; KP[d0 + 1][cc] = g.y;
                KP[d0 + 2][cc] = g.z; KP[d0 + 3][cc] = g.w;
            }
        }
#pragma unroll
        for (int i = 0; i < 4; i++) {
            int f  = tid + (i << 8);
            int vc = f >> 4;
            int vd = (f & 15) << 2;
            float4 g = *(const float4*)(base + (size_t)(kb + vc) * 3 * CC
                                        + 2 * CC + h * DD + vd);
            *(float4*)&Vs[vc][vd] = g;
        }
        __syncthreads();

        float S[4][4];
#pragma unroll
        for (int i = 0; i < 4; i++)
#pragma unroll
            for (int j = 0; j < 4; j++) S[i][j] = 0.f;
#pragma unroll 8
        for (int d = 0; d < 64; d++) {
            float4 a  = *(const float4*)&Qt[d][(ty << 2)];
            float4 bq = *(const float4*)&KP[d][(tx << 2)];
            float av[4] = {a.x, a.y, a.z, a.w};
            float bv[4] = {bq.x, bq.y, bq.z, bq.w};
#pragma unroll
            for (int i = 0; i < 4; i++)
#pragma unroll
                for (int j = 0; j < 4; j++)
                    S[i][j] = fmaf(av[i], bv[j], S[i][j]);
        }
        const float scale = 0.125f;
        if (kt == qtile) {
#pragma unroll
            for (int i = 0; i < 4; i++) {
                int q = qb + (ty << 2) + i;
#pragma unroll
                for (int j = 0; j < 4; j++) {
                    int kk = kb + (tx << 2) + j;
                    S[i][j] = (kk <= q) ? S[i][j] * scale : -1e30f;
                }
            }
        } else {
#pragma unroll
            for (int i = 0; i < 4; i++)
#pragma unroll
                for (int j = 0; j < 4; j++) S[i][j] *= scale;
        }

        float alpha[4];
#pragma unroll
        for (int i = 0; i < 4; i++) {
            float pm = fmaxf(fmaxf(S[i][0], S[i][1]), fmaxf(S[i][2], S[i][3]));
#pragma unroll
            for (int o = 1; o < 16; o <<= 1)
                pm = fmaxf(pm, __shfl_xor_sync(0xffffffffu, pm, o));
            float mn = fmaxf(m[i], pm);
            alpha[i] = __expf(m[i] - mn);
            float rs = 0.f;
#pragma unroll
            for (int j = 0; j < 4; j++) { S[i][j] = __expf(S[i][j] - mn); rs += S[i][j]; }
#pragma unroll
            for (int o = 1; o < 16; o <<= 1)
                rs += __shfl_xor_sync(0xffffffffu, rs, o);
            l[i] = l[i] * alpha[i] + rs;
            m[i] = mn;
#pragma unroll
            for (int j = 0; j < 4; j++) O[i][j] *= alpha[i];
        }

        __syncthreads();
#pragma unroll
        for (int i = 0; i < 4; i++)
            *(float4*)&KP[(ty << 2) + i][(tx << 2)] =
                make_float4(S[i][0], S[i][1], S[i][2], S[i][3]);
        __syncthreads();

#pragma unroll 4
        for (int c = 0; c < 64; c++) {
            float4 v = *(const float4*)&Vs[c][(tx << 2)];
            float vv[4] = {v.x, v.y, v.z, v.w};
#pragma unroll
            for (int i = 0; i < 4; i++) {
                float p = KP[(ty << 2) + i][c];
#pragma unroll
                for (int j = 0; j < 4; j++)
                    O[i][j] = fmaf(p, vv[j], O[i][j]);
            }
        }
    }

#pragma unroll
    for (int i = 0; i < 4; i++) {
        float inv = 1.0f / l[i];
        size_t o = ((size_t)b * TT + qb + (ty << 2) + i) * CC
                 + h * DD + (tx << 2);
        uint32_t hp, lp;
        split2(O[i][0] * inv, O[i][1] * inv, hp, lp);
        *(uint32_t*)(outh + o) = hp;     *(uint32_t*)(outl + o) = lp;
        split2(O[i][2] * inv, O[i][3] * inv, hp, lp);
        *(uint32_t*)(outh + o + 2) = hp; *(uint32_t*)(outl + o + 2) = lp;
    }
}

// ---------------------------------------------------------------------------
// Fused LayerNorm + residual: h += LN(y)*g + beta ; writes fp32 + hi/lo
// ---------------------------------------------------------------------------
__global__ void __launch_bounds__(256) ln_res_kernel(
    const float* __restrict__ y, const float* __restrict__ g,
    const float* __restrict__ be, float* __restrict__ h,
    __nv_bfloat16* __restrict__ hh, __nv_bfloat16* __restrict__ hl)
{
    __shared__ float red1[8];
    __shared__ float red2[8];
    const int row = blockIdx.x;
    const int tid = threadIdx.x;
    const float* yr = y + (size_t)row * CC;

    float v0 = yr[tid], v1 = yr[tid + 256], v2 = yr[tid + 512];
    float s = v0 + v1 + v2;
#pragma unroll
    for (int o = 16; o; o >>= 1) s += __shfl_xor_sync(0xffffffffu, s, o);
    if ((tid & 31) == 0) red1[tid >> 5] = s;
    __syncthreads();
    float tot = 0.f;
#pragma unroll
    for (int i = 0; i < 8; i++) tot += red1[i];
    float mu = tot * (1.0f / 768.0f);

    float d0 = v0 - mu, d1 = v1 - mu, d2 = v2 - mu;
    float q = d0 * d0 + d1 * d1 + d2 * d2;
#pragma unroll
    for (int o = 16; o; o >>= 1) q += __shfl_xor_sync(0xffffffffu, q, o);
    if ((tid & 31) == 0) red2[tid >> 5] = q;
    __syncthreads();
    float qt = 0.f;
#pragma unroll
    for (int i = 0; i < 8; i++) qt += red2[i];
    float rstd = rsqrtf(qt * (1.0f / 768.0f) + 1e-5f);

    float* hr = h + (size_t)row * CC;
    size_t ob = (size_t)row * CC;
#pragma unroll
    for (int p = 0; p < 3; p++) {
        int c = tid + p * 256;
        float dd = (p == 0) ? d0 : (p == 1) ? d1 : d2;
        float nv = hr[c] + dd * rstd * g[c] + be[c];
        hr[c] = nv;
        __nv_bfloat16 hb = __float2bfloat16_rn(nv);
        hh[ob + c] = hb;
        hl[ob + c] = __float2bfloat16_rn(nv - __bfloat162float(hb));
    }
}

// ---------------------------------------------------------------------------
// Launch
// ---------------------------------------------------------------------------
extern "C" void kernel_launch(void* const* d_in, const int* in_sizes, int n_in,
                              void* d_out, int out_size)
{
    const int*   x     = (const int*)  d_in[0];
    const float* embed = (const float*)d_in[1];
    const float* pos   = (const float*)d_in[2];
    const float* Wqkv  = (const float*)d_in[3];
    const float* bqkv  = (const float*)d_in[4];
    const float* W1a   = (const float*)d_in[5];
    const float* b1a   = (const float*)d_in[6];
    const float* W2a   = (const float*)d_in[7];
    const float* b2a   = (const float*)d_in[8];
    const float* g1    = (const float*)d_in[9];
    const float* beta1 = (const float*)d_in[10];
    const float* W1b   = (const float*)d_in[11];
    const float* b1b   = (const float*)d_in[12];
    const float* W2b   = (const float*)d_in[13];
    const float* b2b   = (const float*)d_in[14];
    const float* g2    = (const float*)d_in[15];
    const float* beta2 = (const float*)d_in[16];
    const float* lmW   = (const float*)d_in[17];
    const float* lmb   = (const float*)d_in[18];
    float* out = (float*)d_out;

    float *h, *qkvb, *tmp;
    __nv_bfloat16 *hh, *hl, *ath, *atl, *mih, *mil;
    cudaGetSymbolAddress((void**)&h,    g_h);
    cudaGetSymbolAddress((void**)&qkvb, g_qkv);
    cudaGetSymbolAddress((void**)&tmp,  g_tmp);
    cudaGetSymbolAddress((void**)&hh,   g_hh);
    cudaGetSymbolAddress((void**)&hl,   g_hl);
    cudaGetSymbolAddress((void**)&ath,  g_ath);
    cudaGetSymbolAddress((void**)&atl,  g_atl);
    cudaGetSymbolAddress((void**)&mih,  g_mih);
    cudaGetSymbolAddress((void**)&mil,  g_mil);

    __nv_bfloat16 *wqh, *wql, *w1ah, *w1al, *w2ah, *w2al,
                  *w1bh, *w1bl, *w2bh, *w2bl, *lmh, *lml;
    cudaGetSymbolAddress((void**)&wqh,  g_wqkv_h);
    cudaGetSymbolAddress((void**)&wql,  g_wqkv_l);
    cudaGetSymbolAddress((void**)&w1ah, g_w1a_h);
    cudaGetSymbolAddress((void**)&w1al, g_w1a_l);
    cudaGetSymbolAddress((void**)&w2ah, g_w2a_h);
    cudaGetSymbolAddress((void**)&w2al, g_w2a_l);
    cudaGetSymbolAddress((void**)&w1bh, g_w1b_h);
    cudaGetSymbolAddress((void**)&w1bl, g_w1b_l);
    cudaGetSymbolAddress((void**)&w2bh, g_w2b_h);
    cudaGetSymbolAddress((void**)&w2bl, g_w2b_l);
    cudaGetSymbolAddress((void**)&lmh,  g_lm_h);
    cudaGetSymbolAddress((void**)&lml,  g_lm_l);

    cudaFuncSetAttribute(hgemm_kernel<0,1,0>,
        cudaFuncAttributeMaxDynamicSharedMemorySize, GSMEM_BYTES);
    cudaFuncSetAttribute(hgemm_kernel<1,0,1>,
        cudaFuncAttributeMaxDynamicSharedMemorySize, GSMEM_BYTES);

    // weight pre-convert
    const dim3 cb(32, 8);
    convert_w_kernel<<<dim3(3 * CC / 32, CC / 32, LNUM), cb>>>(Wqkv, wqh, wql, CC, 3 * CC);
    convert_w_kernel<<<dim3(FFF / 32, CC / 32, LNUM), cb>>>(W1a, w1ah, w1al, CC, FFF);
    convert_w_kernel<<<dim3(CC / 32, FFF / 32, LNUM), cb>>>(W2a, w2ah, w2al, FFF, CC);
    convert_w_kernel<<<dim3(FFF / 32, CC / 32, LNUM), cb>>>(W1b, w1bh, w1bl, CC, FFF);
    convert_w_kernel<<<dim3(CC / 32, FFF / 32, LNUM), cb>>>(W2b, w2bh, w2bl, FFF, CC);
    convert_w_kernel<<<dim3(VV / 32, CC / 32, 1),     cb>>>(lmW, lmh, lml, CC, VV);

    embed_kernel<<<BT, 192>>>(x, embed, pos, h, hh, hl);

    const dim3 grid_qkv (3 * CC / 128, BT / 128);
    const dim3 grid_ffn1(FFF / 128,    BT / 128);
    const dim3 grid_ffn2(CC / 128,     BT / 128);
    const dim3 grid_lm  (VV / 128,     BT / 128);
    const dim3 grid_attn(TT / 64, BB * HH);

    for (int l = 0; l < LNUM; l++) {
        // qkv: A=h(hi/lo), out fp32
        hgemm_kernel<0,1,0><<<grid_qkv, 256, GSMEM_BYTES>>>(
            hh, hl, wqh + (size_t)l * 3 * CC * CC, wql + (size_t)l * 3 * CC * CC,
            bqkv + (size_t)l * 3 * CC, qkvb, nullptr, nullptr, 3 * CC, CC);
        attn_kernel<<<grid_attn, 256>>>(qkvb, ath, atl);
        // ffn1a: A=att, GELU, out hi/lo
        hgemm_kernel<1,0,1><<<grid_ffn1, 256, GSMEM_BYTES>>>(
            ath, atl, w1ah + (size_t)l * CC * FFF, w1al + (size_t)l * CC * FFF,
            b1a + (size_t)l * FFF, nullptr, mih, mil, FFF, CC);
        // ffn2a: A=mid, out fp32
        hgemm_kernel<0,1,0><<<grid_ffn2, 256, GSMEM_BYTES>>>(
            mih, mil, w2ah + (size_t)l * CC * FFF, w2al + (size_t)l * CC * FFF,
            b2a + (size_t)l * CC, tmp, nullptr, nullptr, CC, FFF);
        ln_res_kernel<<<BT, 256>>>(tmp, g1 + (size_t)l * CC,
                                   beta1 + (size_t)l * CC, h, hh, hl);
        // ffn1b: A=h, GELU, out hi/lo
        hgemm_kernel<1,0,1><<<grid_ffn1, 256, GSMEM_BYTES>>>(
            hh, hl, w1bh + (size_t)l * CC * FFF, w1bl + (size_t)l * CC * FFF,
            b1b + (size_t)l * FFF, nullptr, mih, mil, FFF, CC);
        // ffn2b: A=mid, out fp32
        hgemm_kernel<0,1,0><<<grid_ffn2, 256, GSMEM_BYTES>>>(
            mih, mil, w2bh + (size_t)l * CC * FFF, w2bl + (size_t)l * CC * FFF,
            b2b + (size_t)l * CC, tmp, nullptr, nullptr, CC, FFF);
        ln_res_kernel<<<BT, 256>>>(tmp, g2 + (size_t)l * CC,
                                   beta2 + (size_t)l * CC, h, hh, hl);
    }

    hgemm_kernel<0,1,0><<<grid_lm, 256, GSMEM_BYTES>>>(
        hh, hl, lmh, lml, lmb, out, nullptr, nullptr, VV, CC);
}

// round 5
// speedup vs baseline: 2.2729x; 1.1805x over previous
#include <cuda_runtime.h>
#include <cuda_bf16.h>
#include <math.h>
#include <stdint.h>

#define LNUM 8
#define BB   8
#define TT   1024
#define CC   768
#define HH   12
#define DD   64
#define VV   1024
#define FFF  3072
#define BT   (BB*TT)   // 8192

// ---------------------------------------------------------------------------
// Scratch activations
// ---------------------------------------------------------------------------
__device__ float g_h  [BT * CC];
__device__ float g_qkv[BT * 3 * CC];
__device__ float g_tmp[BT * CC];
__device__ __nv_bfloat16 g_hh [BT * CC];
__device__ __nv_bfloat16 g_hl [BT * CC];
__device__ __nv_bfloat16 g_ath[BT * CC];
__device__ __nv_bfloat16 g_atl[BT * CC];
__device__ __nv_bfloat16 g_mih[BT * FFF];
__device__ __nv_bfloat16 g_mil[BT * FFF];

// ---------------------------------------------------------------------------
// Pre-converted weights: transposed [N][K], bf16 hi/lo split
// ---------------------------------------------------------------------------
__device__ __nv_bfloat16 g_wqkv_h[LNUM * 3 * CC * CC];
__device__ __nv_bfloat16 g_wqkv_l[LNUM * 3 * CC * CC];
__device__ __nv_bfloat16 g_w1a_h [LNUM * CC * FFF];
__device__ __nv_bfloat16 g_w1a_l [LNUM * CC * FFF];
__device__ __nv_bfloat16 g_w2a_h [LNUM * CC * FFF];
__device__ __nv_bfloat16 g_w2a_l [LNUM * CC * FFF];
__device__ __nv_bfloat16 g_w1b_h [LNUM * CC * FFF];
__device__ __nv_bfloat16 g_w1b_l [LNUM * CC * FFF];
__device__ __nv_bfloat16 g_w2b_h [LNUM * CC * FFF];
__device__ __nv_bfloat16 g_w2b_l [LNUM * CC * FFF];
__device__ __nv_bfloat16 g_lm_h  [VV * CC];
__device__ __nv_bfloat16 g_lm_l  [VV * CC];

// ---------------------------------------------------------------------------
// Helpers
// ---------------------------------------------------------------------------
__device__ __forceinline__ float gelu_f(float x) {
    return 0.5f * x * (1.0f + erff(x * 0.70710678118654752f));
}

__device__ __forceinline__ uint32_t smem_u32(const void* p) {
    uint32_t a;
    asm("{ .reg .u64 t; cvta.to.shared.u64 t, %1; cvt.u32.u64 %0, t; }"
        : "=r"(a) : "l"(p));
    return a;
}

__device__ __forceinline__ void cpa16(uint32_t s, const void* g) {
    asm volatile("cp.async.cg.shared.global [%0], [%1], 16;"
                 :: "r"(s), "l"(g));
}
#define CP_COMMIT() asm volatile("cp.async.commit_group;" ::: "memory")
#define CP_WAIT1()  asm volatile("cp.async.wait_group 1;" ::: "memory")

__device__ __forceinline__ void ldsm4(uint32_t* r, uint32_t a) {
    asm volatile("ldmatrix.sync.aligned.m8n8.x4.shared.b16 {%0,%1,%2,%3}, [%4];"
        : "=r"(r[0]), "=r"(r[1]), "=r"(r[2]), "=r"(r[3]) : "r"(a));
}

__device__ __forceinline__ void mma16816(float* c, const uint32_t* a,
                                         uint32_t b0, uint32_t b1) {
    asm volatile(
        "mma.sync.aligned.m16n8k16.row.col.f32.bf16.bf16.f32 "
        "{%0,%1,%2,%3}, {%4,%5,%6,%7}, {%8,%9}, {%0,%1,%2,%3};"
        : "+f"(c[0]), "+f"(c[1]), "+f"(c[2]), "+f"(c[3])
        : "r"(a[0]), "r"(a[1]), "r"(a[2]), "r"(a[3]), "r"(b0), "r"(b1));
}

__device__ __forceinline__ uint32_t pack_bf2(float a, float b) {
    __nv_bfloat162 p = __floats2bfloat162_rn(a, b);
    return *reinterpret_cast<uint32_t*>(&p);
}
__device__ __forceinline__ void split2(float v0, float v1,
                                       uint32_t& hp, uint32_t& lp) {
    __nv_bfloat16 h0 = __float2bfloat16_rn(v0);
    __nv_bfloat16 h1 = __float2bfloat16_rn(v1);
    float l0 = v0 - __bfloat162float(h0);
    float l1 = v1 - __bfloat162float(h1);
    __nv_bfloat162 hh = __halves2bfloat162(h0, h1);
    hp = *reinterpret_cast<uint32_t*>(&hh);
    lp = pack_bf2(l0, l1);
}

// smem swizzle: row of 64B (32 bf16), 4 chunks of 16B, chunk ^= (row>>1)&3
__device__ __forceinline__ uint32_t swz(int row, int c) {
    return (uint32_t)((row << 6) + (((c ^ ((row >> 1) & 3)) << 4)));
}

// ---------------------------------------------------------------------------
// Weight pre-convert: W[K][N] fp32 -> Wt_hi[N][K], Wt_lo[N][K] bf16
// ---------------------------------------------------------------------------
__device__ __forceinline__ void convert_body(
    const float* __restrict__ Wl, __nv_bfloat16* __restrict__ hl,
    __nv_bfloat16* __restrict__ ll, int K, int N)
{
    __shared__ float t[32][33];
    const int kb = blockIdx.y << 5, nb = blockIdx.x << 5;
    const int tx = threadIdx.x, ty = threadIdx.y;
#pragma unroll
    for (int i = 0; i < 32; i += 8)
        t[ty + i][tx] = Wl[(size_t)(kb + ty + i) * N + nb + tx];
    __syncthreads();
#pragma unroll
    for (int i = 0; i < 32; i += 8) {
        float v = t[tx][ty + i];
        __nv_bfloat16 h = __float2bfloat16_rn(v);
        __nv_bfloat16 l = __float2bfloat16_rn(v - __bfloat162float(h));
        size_t o = (size_t)(nb + ty + i) * K + kb + tx;
        hl[o] = h; ll[o] = l;
    }
}

__global__ void __launch_bounds__(256) convert_w_kernel(
    const float* __restrict__ W, __nv_bfloat16* __restrict__ hi,
    __nv_bfloat16* __restrict__ lo, int K, int N)
{
    const size_t loff = (size_t)blockIdx.z * K * N;
    convert_body(W + loff, hi + loff, lo + loff, K, N);
}

// two weight sets of identical shape, z in [0, 2L)
__global__ void __launch_bounds__(256) convert_w2_kernel(
    const float* __restrict__ Wa, const float* __restrict__ Wb,
    __nv_bfloat16* __restrict__ hia, __nv_bfloat16* __restrict__ loa,
    __nv_bfloat16* __restrict__ hib, __nv_bfloat16* __restrict__ lob,
    int K, int N)
{
    int z = blockIdx.z;
    const float* W; __nv_bfloat16 *hi, *lo;
    if (z < LNUM) {
        size_t o = (size_t)z * K * N;
        W = Wa + o; hi = hia + o; lo = loa + o;
    } else {
        size_t o = (size_t)(z - LNUM) * K * N;
        W = Wb + o; hi = hib + o; lo = lob + o;
    }
    convert_body(W, hi, lo, K, N);
}

// ---------------------------------------------------------------------------
// HMMA GEMM v3: C = epi(A(hi+lo) @ Bt(hi+lo) + bias)
// CTA 128xNT, BK=32, 8 warps (4x2). 3-stage cp.async pipeline, ONE barrier
// per iteration, XOR-swizzled 64B smem rows (no padding).
// ---------------------------------------------------------------------------
template<int EPI, int WF32, int WHL, int NT>
__global__ void __launch_bounds__(256, 2) hgemm_kernel(
    const __nv_bfloat16* __restrict__ Ah, const __nv_bfloat16* __restrict__ Al,
    const __nv_bfloat16* __restrict__ Bh, const __nv_bfloat16* __restrict__ Bl,
    const float* __restrict__ bias, float* __restrict__ C,
    __nv_bfloat16* __restrict__ Ch, __nv_bfloat16* __restrict__ Cl,
    int N, int K)
{
    constexpr int WN  = NT / 2;        // warp n extent
    constexpr int NI  = WN / 8;        // n8 tiles per warp
    constexpr int NIP = WN / 16;       // n16 ldsm groups per warp
    constexpr int TA  = 128 * 64;      // 8192 B per A tile
    constexpr int TB  = NT * 64;       // B tile bytes
    constexpr int STG = 2 * TA + 2 * TB;

    extern __shared__ __align__(128) char smem[];
    const int tid  = threadIdx.x;
    const int lane = tid & 31;
    const int wid  = tid >> 5;
    const int wm   = wid & 3, wn = wid >> 2;
    const int g    = lane >> 2, t = lane & 3;
    const int bm   = blockIdx.y << 7, bn = blockIdx.x * NT;
    const uint32_t sbase = smem_u32(smem);

    const __nv_bfloat16* gpA[2] = { Ah + (size_t)bm * K, Al + (size_t)bm * K };
    const __nv_bfloat16* gpB[2] = { Bh + (size_t)bn * K, Bl + (size_t)bn * K };

    float acc[2][NI][4];
#pragma unroll
    for (int mi = 0; mi < 2; mi++)
#pragma unroll
        for (int ni = 0; ni < NI; ni++)
#pragma unroll
            for (int r = 0; r < 4; r++) acc[mi][ni][r] = 0.f;

    const int nk = K >> 5;

    // staging: each thread copies 16B chunks; A: 128 rows, B: NT rows
    const int srow = tid >> 2, schk = tid & 3;

    auto stage = [&](int kt, int buf) {
        uint32_t s0 = sbase + buf * STG;
        const int kc = kt * 32 + schk * 8;
#pragma unroll
        for (int m = 0; m < 2; m++) {
#pragma unroll
            for (int i = 0; i < 2; i++) {
                int row = srow + i * 64;
                cpa16(s0 + m * TA + swz(row, schk),
                      gpA[m] + (size_t)row * K + kc);
            }
#pragma unroll
            for (int i = 0; i < NT / 64; i++) {
                int row = srow + i * 64;
                cpa16(s0 + 2 * TA + m * TB + swz(row, schk),
                      gpB[m] + (size_t)row * K + kc);
            }
        }
        CP_COMMIT();
    };

    stage(0, 0);
    stage(1, 1);

    // fragment addressing
    const int arow0 = wm * 32 + (lane & 15);
    const int akh   = lane >> 4;
    const int brow0 = wn * WN + (lane & 7) + ((lane >> 4) << 3);
    const int bkh   = (lane >> 3) & 1;

    int buf = 0;
    for (int kt = 0; kt < nk; kt++) {
        CP_WAIT1();
        __syncthreads();

        const uint32_t st  = sbase + buf * STG;
        const uint32_t Ahp = st, Alp = st + TA;
        const uint32_t Bhp = st + 2 * TA, Blp = st + 2 * TA + TB;

#pragma unroll
        for (int ks = 0; ks < 2; ks++) {
            uint32_t ah[2][4], al[2][4];
#pragma unroll
            for (int mi = 0; mi < 2; mi++) {
                int row = arow0 + mi * 16;
                uint32_t ao = swz(row, ks * 2 + akh);
                ldsm4(ah[mi], Ahp + ao);
                ldsm4(al[mi], Alp + ao);
            }
#pragma unroll
            for (int nip = 0; nip < NIP; nip++) {
                int row = brow0 + nip * 16;
                uint32_t bo = swz(row, ks * 2 + bkh);
                uint32_t bh[4], bl[4];
                ldsm4(bh, Bhp + bo);
                ldsm4(bl, Blp + bo);
#pragma unroll
                for (int mi = 0; mi < 2; mi++) {
                    mma16816(acc[mi][2 * nip],     ah[mi], bh[0], bh[1]);
                    mma16816(acc[mi][2 * nip],     ah[mi], bl[0], bl[1]);
                    mma16816(acc[mi][2 * nip],     al[mi], bh[0], bh[1]);
                    mma16816(acc[mi][2 * nip + 1], ah[mi], bh[2], bh[3]);
                    mma16816(acc[mi][2 * nip + 1], ah[mi], bl[2], bl[3]);
                    mma16816(acc[mi][2 * nip + 1], al[mi], bh[2], bh[3]);
                }
            }
        }

        // stage kt+2 into the free buffer (not read this iter or next)
        int nbuf = buf + 2; if (nbuf >= 3) nbuf -= 3;
        if (kt + 2 < nk) stage(kt + 2, nbuf); else CP_COMMIT();
        buf = buf + 1; if (buf == 3) buf = 0;
    }

    // epilogue
#pragma unroll
    for (int ni = 0; ni < NI; ni++) {
        int col = bn + wn * WN + ni * 8 + t * 2;
        float b0 = bias[col], b1 = bias[col + 1];
#pragma unroll
        for (int mi = 0; mi < 2; mi++) {
            int r0 = bm + wm * 32 + mi * 16 + g;
            float v0 = acc[mi][ni][0] + b0;
            float v1 = acc[mi][ni][1] + b1;
            float v2 = acc[mi][ni][2] + b0;
            float v3 = acc[mi][ni][3] + b1;
            if (EPI == 1) {
                v0 = gelu_f(v0); v1 = gelu_f(v1);
                v2 = gelu_f(v2); v3 = gelu_f(v3);
            }
            size_t o0 = (size_t)r0 * N + col;
            size_t o1 = (size_t)(r0 + 8) * N + col;
            if (WF32) {
                *(float2*)(C + o0) = make_float2(v0, v1);
                *(float2*)(C + o1) = make_float2(v2, v3);
            }
            if (WHL) {
                uint32_t hp, lp;
                split2(v0, v1, hp, lp);
                *(uint32_t*)(Ch + o0) = hp;
                *(uint32_t*)(Cl + o0) = lp;
                split2(v2, v3, hp, lp);
                *(uint32_t*)(Ch + o1) = hp;
                *(uint32_t*)(Cl + o1) = lp;
            }
        }
    }
}

// ---------------------------------------------------------------------------
// Embedding
// ---------------------------------------------------------------------------
__global__ void __launch_bounds__(192) embed_kernel(
    const int* __restrict__ x, const float* __restrict__ emb,
    const float* __restrict__ pos, float* __restrict__ h,
    __nv_bfloat16* __restrict__ hh, __nv_bfloat16* __restrict__ hl)
{
    const int bt  = blockIdx.x;
    const int tok = x[bt];
    const int t   = bt & (TT - 1);
    const float4* e4 = (const float4*)(emb + (size_t)tok * CC);
    const float4* p4 = (const float4*)(pos + (size_t)t   * CC);
    const int i = threadIdx.x;
    float4 a = e4[i], b = p4[i];
    float4 s = make_float4(a.x + b.x, a.y + b.y, a.z + b.z, a.w + b.w);
    ((float4*)(h + (size_t)bt * CC))[i] = s;
    size_t o = (size_t)bt * CC + i * 4;
    uint32_t hp, lp;
    split2(s.x, s.y, hp, lp);
    *(uint32_t*)(hh + o) = hp;     *(uint32_t*)(hl + o) = lp;
    split2(s.z, s.w, hp, lp);
    *(uint32_t*)(hh + o + 2) = hp; *(uint32_t*)(hl + o + 2) = lp;
}

// ---------------------------------------------------------------------------
// Fused causal flash attention (fp32 SIMT) -> bf16 hi/lo output
// ---------------------------------------------------------------------------
__global__ void __launch_bounds__(256) attn_kernel(
    const float* __restrict__ qkv,
    __nv_bfloat16* __restrict__ outh, __nv_bfloat16* __restrict__ outl)
{
    __shared__ float Qt[64][64];
    __shared__ float KP[64][64];
    __shared__ float Vs[64][64];

    const int tid   = threadIdx.x;
    const int qtile = blockIdx.x;
    const int bh    = blockIdx.y;
    const int b     = bh / HH;
    const int h     = bh % HH;
    const int qb    = qtile << 6;
    const float* base = qkv + (size_t)b * TT * 3 * CC;

    const int cc   = tid & 63;
    const int dblk = tid >> 6;

    {
        const float* Qg = base + (size_t)(qb + cc) * 3 * CC + CC + h * DD;
#pragma unroll
        for (int i = 0; i < 4; i++) {
            int d0 = (dblk + (i << 2)) << 2;
            float4 g = *(const float4*)(Qg + d0);
            Qt[d0 + 0][cc] = g.x; Qt[d0 + 1][cc] = g.y;
            Qt[d0 + 2][cc] = g.z; Qt[d0 + 3][cc] = g.w;
        }
    }

    const int tx = tid & 15, ty = tid >> 4;
    float m[4], l[4], O[4][4];
#pragma unroll
    for (int i = 0; i < 4; i++) {
        m[i] = -1e30f; l[i] = 0.f;
#pragma unroll
        for (int j = 0; j < 4; j++) O[i][j] = 0.f;
    }

    for (int kt = 0; kt <= qtile; kt++) {
        const int kb = kt << 6;
        __syncthreads();
        {
            const float* Kg = base + (size_t)(kb + cc) * 3 * CC + h * DD;
#pragma unroll
            for (int i = 0; i < 4; i++) {
                int d0 = (dblk + (i << 2)) << 2;
                float4 g = *(const float4*)(Kg + d0);
                KP[d0 + 0][cc] = g.x; KP[d0 + 1][cc] = g.y;
                KP[d0 + 2][cc] = g.z; KP[d0 + 3][cc] = g.w;
            }
        }
#pragma unroll
        for (int i = 0; i < 4; i++) {
            int f  = tid + (i << 8);
            int vc = f >> 4;
            int vd = (f & 15) << 2;
            float4 g = *(const float4*)(base + (size_t)(kb + vc) * 3 * CC
                                        + 2 * CC + h * DD + vd);
            *(float4*)&Vs[vc][vd] = g;
        }
        __syncthreads();

        float S[4][4];
#pragma unroll
        for (int i = 0; i < 4; i++)
#pragma unroll
            for (int j = 0; j < 4; j++) S[i][j] = 0.f;
#pragma unroll 8
        for (int d = 0; d < 64; d++) {
            float4 a  = *(const float4*)&Qt[d][(ty << 2)];
            float4 bq = *(const float4*)&KP[d][(tx << 2)];
            float av[4] = {a.x, a.y, a.z, a.w};
            float bv[4] = {bq.x, bq.y, bq.z, bq.w};
#pragma unroll
            for (int i = 0; i < 4; i++)
#pragma unroll
                for (int j = 0; j < 4; j++)
                    S[i][j] = fmaf(av[i], bv[j], S[i][j]);
        }
        const float scale = 0.125f;
        if (kt == qtile) {
#pragma unroll
            for (int i = 0; i < 4; i++) {
                int q = qb + (ty << 2) + i;
#pragma unroll
                for (int j = 0; j < 4; j++) {
                    int kk = kb + (tx << 2) + j;
                    S[i][j] = (kk <= q) ? S[i][j] * scale : -1e30f;
                }
            }
        } else {
#pragma unroll
            for (int i = 0; i < 4; i++)
#pragma unroll
                for (int j = 0; j < 4; j++) S[i][j] *= scale;
        }

        float alpha[4];
#pragma unroll
        for (int i = 0; i < 4; i++) {
            float pm = fmaxf(fmaxf(S[i][0], S[i][1]), fmaxf(S[i][2], S[i][3]));
#pragma unroll
            for (int o = 1; o < 16; o <<= 1)
                pm = fmaxf(pm, __shfl_xor_sync(0xffffffffu, pm, o));
            float mn = fmaxf(m[i], pm);
            alpha[i] = __expf(m[i] - mn);
            float rs = 0.f;
#pragma unroll
            for (int j = 0; j < 4; j++) { S[i][j] = __expf(S[i][j] - mn); rs += S[i][j]; }
#pragma unroll
            for (int o = 1; o < 16; o <<= 1)
                rs += __shfl_xor_sync(0xffffffffu, rs, o);
            l[i] = l[i] * alpha[i] + rs;
            m[i] = mn;
#pragma unroll
            for (int j = 0; j < 4; j++) O[i][j] *= alpha[i];
        }

        __syncthreads();
#pragma unroll
        for (int i = 0; i < 4; i++)
            *(float4*)&KP[(ty << 2) + i][(tx << 2)] =
                make_float4(S[i][0], S[i][1], S[i][2], S[i][3]);
        __syncthreads();

#pragma unroll 4
        for (int c = 0; c < 64; c++) {
            float4 v = *(const float4*)&Vs[c][(tx << 2)];
            float vv[4] = {v.x, v.y, v.z, v.w};
#pragma unroll
            for (int i = 0; i < 4; i++) {
                float p = KP[(ty << 2) + i][c];
#pragma unroll
                for (int j = 0; j < 4; j++)
                    O[i][j] = fmaf(p, vv[j], O[i][j]);
            }
        }
    }

#pragma unroll
    for (int i = 0; i < 4; i++) {
        float inv = 1.0f / l[i];
        size_t o = ((size_t)b * TT + qb + (ty << 2) + i) * CC
                 + h * DD + (tx << 2);
        uint32_t hp, lp;
        split2(O[i][0] * inv, O[i][1] * inv, hp, lp);
        *(uint32_t*)(outh + o) = hp;     *(uint32_t*)(outl + o) = lp;
        split2(O[i][2] * inv, O[i][3] * inv, hp, lp);
        *(uint32_t*)(outh + o + 2) = hp; *(uint32_t*)(outl + o + 2) = lp;
    }
}

// ---------------------------------------------------------------------------
// Fused LayerNorm + residual: h += LN(y)*g + beta ; writes fp32 + hi/lo
// ---------------------------------------------------------------------------
__global__ void __launch_bounds__(256) ln_res_kernel(
    const float* __restrict__ y, const float* __restrict__ g,
    const float* __restrict__ be, float* __restrict__ h,
    __nv_bfloat16* __restrict__ hh, __nv_bfloat16* __restrict__ hl)
{
    __shared__ float red1[8];
    __shared__ float red2[8];
    const int row = blockIdx.x;
    const int tid = threadIdx.x;
    const float* yr = y + (size_t)row * CC;

    float v0 = yr[tid], v1 = yr[tid + 256], v2 = yr[tid + 512];
    float s = v0 + v1 + v2;
#pragma unroll
    for (int o = 16; o; o >>= 1) s += __shfl_xor_sync(0xffffffffu, s, o);
    if ((tid & 31) == 0) red1[tid >> 5] = s;
    __syncthreads();
    float tot = 0.f;
#pragma unroll
    for (int i = 0; i < 8; i++) tot += red1[i];
    float mu = tot * (1.0f / 768.0f);

    float d0 = v0 - mu, d1 = v1 - mu, d2 = v2 - mu;
    float q = d0 * d0 + d1 * d1 + d2 * d2;
#pragma unroll
    for (int o = 16; o; o >>= 1) q += __shfl_xor_sync(0xffffffffu, q, o);
    if ((tid & 31) == 0) red2[tid >> 5] = q;
    __syncthreads();
    float qt = 0.f;
#pragma unroll
    for (int i = 0; i < 8; i++) qt += red2[i];
    float rstd = rsqrtf(qt * (1.0f / 768.0f) + 1e-5f);

    float* hr = h + (size_t)row * CC;
    size_t ob = (size_t)row * CC;
#pragma unroll
    for (int p = 0; p < 3; p++) {
        int c = tid + p * 256;
        float dd = (p == 0) ? d0 : (p == 1) ? d1 : d2;
        float nv = hr[c] + dd * rstd * g[c] + be[c];
        hr[c] = nv;
        __nv_bfloat16 hb = __float2bfloat16_rn(nv);
        hh[ob + c] = hb;
        hl[ob + c] = __float2bfloat16_rn(nv - __bfloat162float(hb));
    }
}

// ---------------------------------------------------------------------------
// Launch
// ---------------------------------------------------------------------------
#define SM128 (3 * (2 * 128 * 64 + 2 * 128 * 64))   // 98304
#define SM64  (3 * (2 * 128 * 64 + 2 * 64 * 64))    // 73728

extern "C" void kernel_launch(void* const* d_in, const int* in_sizes, int n_in,
                              void* d_out, int out_size)
{
    const int*   x     = (const int*)  d_in[0];
    const float* embed = (const float*)d_in[1];
    const float* pos   = (const float*)d_in[2];
    const float* Wqkv  = (const float*)d_in[3];
    const float* bqkv  = (const float*)d_in[4];
    const float* W1a   = (const float*)d_in[5];
    const float* b1a   = (const float*)d_in[6];
    const float* W2a   = (const float*)d_in[7];
    const float* b2a   = (const float*)d_in[8];
    const float* g1    = (const float*)d_in[9];
    const float* beta1 = (const float*)d_in[10];
    const float* W1b   = (const float*)d_in[11];
    const float* b1b   = (const float*)d_in[12];
    const float* W2b   = (const float*)d_in[13];
    const float* b2b   = (const float*)d_in[14];
    const float* g2    = (const float*)d_in[15];
    const float* beta2 = (const float*)d_in[16];
    const float* lmW   = (const float*)d_in[17];
    const float* lmb   = (const float*)d_in[18];
    float* out = (float*)d_out;

    float *h, *qkvb, *tmp;
    __nv_bfloat16 *hh, *hl, *ath, *atl, *mih, *mil;
    cudaGetSymbolAddress((void**)&h,    g_h);
    cudaGetSymbolAddress((void**)&qkvb, g_qkv);
    cudaGetSymbolAddress((void**)&tmp,  g_tmp);
    cudaGetSymbolAddress((void**)&hh,   g_hh);
    cudaGetSymbolAddress((void**)&hl,   g_hl);
    cudaGetSymbolAddress((void**)&ath,  g_ath);
    cudaGetSymbolAddress((void**)&atl,  g_atl);
    cudaGetSymbolAddress((void**)&mih,  g_mih);
    cudaGetSymbolAddress((void**)&mil,  g_mil);

    __nv_bfloat16 *wqh, *wql, *w1ah, *w1al, *w2ah, *w2al,
                  *w1bh, *w1bl, *w2bh, *w2bl, *lmh, *lml;
    cudaGetSymbolAddress((void**)&wqh,  g_wqkv_h);
    cudaGetSymbolAddress((void**)&wql,  g_wqkv_l);
    cudaGetSymbolAddress((void**)&w1ah, g_w1a_h);
    cudaGetSymbolAddress((void**)&w1al, g_w1a_l);
    cudaGetSymbolAddress((void**)&w2ah, g_w2a_h);
    cudaGetSymbolAddress((void**)&w2al, g_w2a_l);
    cudaGetSymbolAddress((void**)&w1bh, g_w1b_h);
    cudaGetSymbolAddress((void**)&w1bl, g_w1b_l);
    cudaGetSymbolAddress((void**)&w2bh, g_w2b_h);
    cudaGetSymbolAddress((void**)&w2bl, g_w2b_l);
    cudaGetSymbolAddress((void**)&lmh,  g_lm_h);
    cudaGetSymbolAddress((void**)&lml,  g_lm_l);

    cudaFuncSetAttribute(hgemm_kernel<0,1,0,128>,
        cudaFuncAttributeMaxDynamicSharedMemorySize, SM128);
    cudaFuncSetAttribute(hgemm_kernel<1,0,1,128>,
        cudaFuncAttributeMaxDynamicSharedMemorySize, SM128);
    cudaFuncSetAttribute(hgemm_kernel<0,1,0,64>,
        cudaFuncAttributeMaxDynamicSharedMemorySize, SM64);

    // weight pre-convert (4 launches), then embed => launch idx 5 = qkv hgemm
    const dim3 cb(32, 8);
    convert_w_kernel<<<dim3(3 * CC / 32, CC / 32, LNUM), cb>>>(
        Wqkv, wqh, wql, CC, 3 * CC);
    convert_w2_kernel<<<dim3(FFF / 32, CC / 32, 2 * LNUM), cb>>>(
        W1a, W1b, w1ah, w1al, w1bh, w1bl, CC, FFF);
    convert_w2_kernel<<<dim3(CC / 32, FFF / 32, 2 * LNUM), cb>>>(
        W2a, W2b, w2ah, w2al, w2bh, w2bl, FFF, CC);
    convert_w_kernel<<<dim3(VV / 32, CC / 32, 1), cb>>>(lmW, lmh, lml, CC, VV);
    embed_kernel<<<BT, 192>>>(x, embed, pos, h, hh, hl);

    const dim3 grid_qkv (3 * CC / 128, BT / 128);
    const dim3 grid_ffn1(FFF / 128,    BT / 128);
    const dim3 grid_ffn2(CC / 64,      BT / 128);   // NT=64
    const dim3 grid_lm  (VV / 128,     BT / 128);
    const dim3 grid_attn(TT / 64, BB * HH);

    for (int l = 0; l < LNUM; l++) {
        hgemm_kernel<0,1,0,128><<<grid_qkv, 256, SM128>>>(
            hh, hl, wqh + (size_t)l * 3 * CC * CC, wql + (size_t)l * 3 * CC * CC,
            bqkv + (size_t)l * 3 * CC, qkvb, nullptr, nullptr, 3 * CC, CC);
        attn_kernel<<<grid_attn, 256>>>(qkvb, ath, atl);
        hgemm_kernel<1,0,1,128><<<grid_ffn1, 256, SM128>>>(
            ath, atl, w1ah + (size_t)l * CC * FFF, w1al + (size_t)l * CC * FFF,
            b1a + (size_t)l * FFF, nullptr, mih, mil, FFF, CC);
        hgemm_kernel<0,1,0,64><<<grid_ffn2, 256, SM64>>>(
            mih, mil, w2ah + (size_t)l * CC * FFF, w2al + (size_t)l * CC * FFF,
            b2a + (size_t)l * CC, tmp, nullptr, nullptr, CC, FFF);
        ln_res_kernel<<<BT, 256>>>(tmp, g1 + (size_t)l * CC,
                                   beta1 + (size_t)l * CC, h, hh, hl);
        hgemm_kernel<1,0,1,128><<<grid_ffn1, 256, SM128>>>(
            hh, hl, w1bh + (size_t)l * CC * FFF, w1bl + (size_t)l * CC * FFF,
            b1b + (size_t)l * FFF, nullptr, mih, mil, FFF, CC);
        hgemm_kernel<0,1,0,64><<<grid_ffn2, 256, SM64>>>(
            mih, mil, w2bh + (size_t)l * CC * FFF, w2bl + (size_t)l * CC * FFF,
            b2b + (size_t)l * CC, tmp, nullptr, nullptr, CC, FFF);
        ln_res_kernel<<<BT, 256>>>(tmp, g2 + (size_t)l * CC,
                                   beta2 + (size_t)l * CC, h, hh, hl);
    }

    hgemm_kernel<0,1,0,128><<<grid_lm, 256, SM128>>>(
        hh, hl, lmh, lml, lmb, out, nullptr, nullptr, VV, CC);
}

// round 6
// speedup vs baseline: 2.4829x; 1.0924x over previous
#include <cuda_runtime.h>
#include <cuda_bf16.h>
#include <math.h>
#include <stdint.h>

#define LNUM 8
#define BB   8
#define TT   1024
#define CC   768
#define HH   12
#define DD   64
#define VV   1024
#define FFF  3072
#define BT   (BB*TT)   // 8192

// ---------------------------------------------------------------------------
// Scratch activations
// ---------------------------------------------------------------------------
__device__ float g_h  [BT * CC];
__device__ float g_tmp[BT * CC];
__device__ __nv_bfloat16 g_hh [BT * CC];
__device__ __nv_bfloat16 g_hl [BT * CC];
__device__ __nv_bfloat16 g_qvh[BT * 3 * CC];   // qkv hi
__device__ __nv_bfloat16 g_qvl[BT * 3 * CC];   // qkv lo
__device__ __nv_bfloat16 g_ath[BT * CC];
__device__ __nv_bfloat16 g_atl[BT * CC];
__device__ __nv_bfloat16 g_mih[BT * FFF];
__device__ __nv_bfloat16 g_mil[BT * FFF];

// ---------------------------------------------------------------------------
// Pre-converted weights: transposed [N][K], bf16 hi/lo split
// ---------------------------------------------------------------------------
__device__ __nv_bfloat16 g_wqkv_h[LNUM * 3 * CC * CC];
__device__ __nv_bfloat16 g_wqkv_l[LNUM * 3 * CC * CC];
__device__ __nv_bfloat16 g_w1a_h [LNUM * CC * FFF];
__device__ __nv_bfloat16 g_w1a_l [LNUM * CC * FFF];
__device__ __nv_bfloat16 g_w2a_h [LNUM * CC * FFF];
__device__ __nv_bfloat16 g_w2a_l [LNUM * CC * FFF];
__device__ __nv_bfloat16 g_w1b_h [LNUM * CC * FFF];
__device__ __nv_bfloat16 g_w1b_l [LNUM * CC * FFF];
__device__ __nv_bfloat16 g_w2b_h [LNUM * CC * FFF];
__device__ __nv_bfloat16 g_w2b_l [LNUM * CC * FFF];
__device__ __nv_bfloat16 g_lm_h  [VV * CC];
__device__ __nv_bfloat16 g_lm_l  [VV * CC];

// ---------------------------------------------------------------------------
// Helpers
// ---------------------------------------------------------------------------
__device__ __forceinline__ float gelu_f(float x) {
    return 0.5f * x * (1.0f + erff(x * 0.70710678118654752f));
}

__device__ __forceinline__ uint32_t smem_u32(const void* p) {
    uint32_t a;
    asm("{ .reg .u64 t; cvta.to.shared.u64 t, %1; cvt.u32.u64 %0, t; }"
        : "=r"(a) : "l"(p));
    return a;
}

__device__ __forceinline__ void cpa16(uint32_t s, const void* g) {
    asm volatile("cp.async.cg.shared.global [%0], [%1], 16;"
                 :: "r"(s), "l"(g));
}
#define CP_COMMIT() asm volatile("cp.async.commit_group;" ::: "memory")
#define CP_WAIT1()  asm volatile("cp.async.wait_group 1;" ::: "memory")

__device__ __forceinline__ void ldsm4(uint32_t* r, uint32_t a) {
    asm volatile("ldmatrix.sync.aligned.m8n8.x4.shared.b16 {%0,%1,%2,%3}, [%4];"
        : "=r"(r[0]), "=r"(r[1]), "=r"(r[2]), "=r"(r[3]) : "r"(a));
}
__device__ __forceinline__ void ldsm4t(uint32_t* r, uint32_t a) {
    asm volatile("ldmatrix.sync.aligned.m8n8.x4.trans.shared.b16 {%0,%1,%2,%3}, [%4];"
        : "=r"(r[0]), "=r"(r[1]), "=r"(r[2]), "=r"(r[3]) : "r"(a));
}

__device__ __forceinline__ void mma16816(float* c, const uint32_t* a,
                                         uint32_t b0, uint32_t b1) {
    asm volatile(
        "mma.sync.aligned.m16n8k16.row.col.f32.bf16.bf16.f32 "
        "{%0,%1,%2,%3}, {%4,%5,%6,%7}, {%8,%9}, {%0,%1,%2,%3};"
        : "+f"(c[0]), "+f"(c[1]), "+f"(c[2]), "+f"(c[3])
        : "r"(a[0]), "r"(a[1]), "r"(a[2]), "r"(a[3]), "r"(b0), "r"(b1));
}

__device__ __forceinline__ uint32_t pack_bf2(float a, float b) {
    __nv_bfloat162 p = __floats2bfloat162_rn(a, b);
    return *reinterpret_cast<uint32_t*>(&p);
}
__device__ __forceinline__ void split2(float v0, float v1,
                                       uint32_t& hp, uint32_t& lp) {
    __nv_bfloat16 h0 = __float2bfloat16_rn(v0);
    __nv_bfloat16 h1 = __float2bfloat16_rn(v1);
    float l0 = v0 - __bfloat162float(h0);
    float l1 = v1 - __bfloat162float(h1);
    __nv_bfloat162 hh = __halves2bfloat162(h0, h1);
    hp = *reinterpret_cast<uint32_t*>(&hh);
    lp = pack_bf2(l0, l1);
}

// GEMM smem swizzle: 64B rows, 4 chunks of 16B, chunk ^= (row>>1)&3
__device__ __forceinline__ uint32_t swz(int row, int c) {
    return (uint32_t)((row << 6) + (((c ^ ((row >> 1) & 3)) << 4)));
}
// Attention smem swizzle: 128B rows, 8 chunks of 16B, chunk ^= row&7
__device__ __forceinline__ uint32_t swz8(int row, int c) {
    return (uint32_t)((row << 7) + (((c ^ (row & 7)) << 4)));
}

// ---------------------------------------------------------------------------
// Weight pre-convert
// ---------------------------------------------------------------------------
__device__ __forceinline__ void convert_body(
    const float* __restrict__ Wl, __nv_bfloat16* __restrict__ hl,
    __nv_bfloat16* __restrict__ ll, int K, int N)
{
    __shared__ float t[32][33];
    const int kb = blockIdx.y << 5, nb = blockIdx.x << 5;
    const int tx = threadIdx.x, ty = threadIdx.y;
#pragma unroll
    for (int i = 0; i < 32; i += 8)
        t[ty + i][tx] = Wl[(size_t)(kb + ty + i) * N + nb + tx];
    __syncthreads();
#pragma unroll
    for (int i = 0; i < 32; i += 8) {
        float v = t[tx][ty + i];
        __nv_bfloat16 h = __float2bfloat16_rn(v);
        __nv_bfloat16 l = __float2bfloat16_rn(v - __bfloat162float(h));
        size_t o = (size_t)(nb + ty + i) * K + kb + tx;
        hl[o] = h; ll[o] = l;
    }
}

__global__ void __launch_bounds__(256) convert_w_kernel(
    const float* __restrict__ W, __nv_bfloat16* __restrict__ hi,
    __nv_bfloat16* __restrict__ lo, int K, int N)
{
    const size_t loff = (size_t)blockIdx.z * K * N;
    convert_body(W + loff, hi + loff, lo + loff, K, N);
}

__global__ void __launch_bounds__(256) convert_w2_kernel(
    const float* __restrict__ Wa, const float* __restrict__ Wb,
    __nv_bfloat16* __restrict__ hia, __nv_bfloat16* __restrict__ loa,
    __nv_bfloat16* __restrict__ hib, __nv_bfloat16* __restrict__ lob,
    int K, int N)
{
    int z = blockIdx.z;
    const float* W; __nv_bfloat16 *hi, *lo;
    if (z < LNUM) {
        size_t o = (size_t)z * K * N;
        W = Wa + o; hi = hia + o; lo = loa + o;
    } else {
        size_t o = (size_t)(z - LNUM) * K * N;
        W = Wb + o; hi = hib + o; lo = lob + o;
    }
    convert_body(W, hi, lo, K, N);
}

// ---------------------------------------------------------------------------
// HMMA GEMM v4: stage-early 3-stage pipeline
// ---------------------------------------------------------------------------
template<int EPI, int WF32, int WHL, int NT>
__global__ void __launch_bounds__(256, 2) hgemm_kernel(
    const __nv_bfloat16* __restrict__ Ah, const __nv_bfloat16* __restrict__ Al,
    const __nv_bfloat16* __restrict__ Bh, const __nv_bfloat16* __restrict__ Bl,
    const float* __restrict__ bias, float* __restrict__ C,
    __nv_bfloat16* __restrict__ Ch, __nv_bfloat16* __restrict__ Cl,
    int N, int K)
{
    constexpr int WN  = NT / 2;
    constexpr int NI  = WN / 8;
    constexpr int NIP = WN / 16;
    constexpr int TA  = 128 * 64;
    constexpr int TB  = NT * 64;
    constexpr int STG = 2 * TA + 2 * TB;

    extern __shared__ __align__(128) char smem[];
    const int tid  = threadIdx.x;
    const int lane = tid & 31;
    const int wid  = tid >> 5;
    const int wm   = wid & 3, wn = wid >> 2;
    const int g    = lane >> 2, t = lane & 3;
    const int bm   = blockIdx.y << 7, bn = blockIdx.x * NT;
    const uint32_t sbase = smem_u32(smem);

    const __nv_bfloat16* gpA[2] = { Ah + (size_t)bm * K, Al + (size_t)bm * K };
    const __nv_bfloat16* gpB[2] = { Bh + (size_t)bn * K, Bl + (size_t)bn * K };

    float acc[2][NI][4];
#pragma unroll
    for (int mi = 0; mi < 2; mi++)
#pragma unroll
        for (int ni = 0; ni < NI; ni++)
#pragma unroll
            for (int r = 0; r < 4; r++) acc[mi][ni][r] = 0.f;

    const int nk = K >> 5;
    const int srow = tid >> 2, schk = tid & 3;

    auto stage = [&](int kt, int buf) {
        uint32_t s0 = sbase + buf * STG;
        const int kc = kt * 32 + schk * 8;
#pragma unroll
        for (int m = 0; m < 2; m++) {
#pragma unroll
            for (int i = 0; i < 2; i++) {
                int row = srow + i * 64;
                cpa16(s0 + m * TA + swz(row, schk),
                      gpA[m] + (size_t)row * K + kc);
            }
#pragma unroll
            for (int i = 0; i < NT / 64; i++) {
                int row = srow + i * 64;
                cpa16(s0 + 2 * TA + m * TB + swz(row, schk),
                      gpB[m] + (size_t)row * K + kc);
            }
        }
        CP_COMMIT();
    };

    stage(0, 0);
    stage(1, 1);

    const int arow0 = wm * 32 + (lane & 15);
    const int akh   = lane >> 4;
    const int brow0 = wn * WN + (lane & 7) + ((lane >> 4) << 3);
    const int bkh   = (lane >> 3) & 1;

    int buf = 0;
    for (int kt = 0; kt < nk; kt++) {
        CP_WAIT1();
        __syncthreads();

        // stage kt+2 FIRST so cp.async overlaps the MMA block
        int nbuf = buf + 2; if (nbuf >= 3) nbuf -= 3;
        if (kt + 2 < nk) stage(kt + 2, nbuf); else CP_COMMIT();

        const uint32_t st  = sbase + buf * STG;
        const uint32_t Ahp = st, Alp = st + TA;
        const uint32_t Bhp = st + 2 * TA, Blp = st + 2 * TA + TB;

#pragma unroll
        for (int ks = 0; ks < 2; ks++) {
            uint32_t ah[2][4], al[2][4];
#pragma unroll
            for (int mi = 0; mi < 2; mi++) {
                int row = arow0 + mi * 16;
                uint32_t ao = swz(row, ks * 2 + akh);
                ldsm4(ah[mi], Ahp + ao);
                ldsm4(al[mi], Alp + ao);
            }
#pragma unroll
            for (int nip = 0; nip < NIP; nip++) {
                int row = brow0 + nip * 16;
                uint32_t bo = swz(row, ks * 2 + bkh);
                uint32_t bh[4], bl[4];
                ldsm4(bh, Bhp + bo);
                ldsm4(bl, Blp + bo);
#pragma unroll
                for (int mi = 0; mi < 2; mi++) {
                    mma16816(acc[mi][2 * nip],     ah[mi], bh[0], bh[1]);
                    mma16816(acc[mi][2 * nip],     ah[mi], bl[0], bl[1]);
                    mma16816(acc[mi][2 * nip],     al[mi], bh[0], bh[1]);
                    mma16816(acc[mi][2 * nip + 1], ah[mi], bh[2], bh[3]);
                    mma16816(acc[mi][2 * nip + 1], ah[mi], bl[2], bl[3]);
                    mma16816(acc[mi][2 * nip + 1], al[mi], bh[2], bh[3]);
                }
            }
        }
        buf = buf + 1; if (buf == 3) buf = 0;
    }

#pragma unroll
    for (int ni = 0; ni < NI; ni++) {
        int col = bn + wn * WN + ni * 8 + t * 2;
        float b0 = bias[col], b1 = bias[col + 1];
#pragma unroll
        for (int mi = 0; mi < 2; mi++) {
            int r0 = bm + wm * 32 + mi * 16 + g;
            float v0 = acc[mi][ni][0] + b0;
            float v1 = acc[mi][ni][1] + b1;
            float v2 = acc[mi][ni][2] + b0;
            float v3 = acc[mi][ni][3] + b1;
            if (EPI == 1) {
                v0 = gelu_f(v0); v1 = gelu_f(v1);
                v2 = gelu_f(v2); v3 = gelu_f(v3);
            }
            size_t o0 = (size_t)r0 * N + col;
            size_t o1 = (size_t)(r0 + 8) * N + col;
            if (WF32) {
                *(float2*)(C + o0) = make_float2(v0, v1);
                *(float2*)(C + o1) = make_float2(v2, v3);
            }
            if (WHL) {
                uint32_t hp, lp;
                split2(v0, v1, hp, lp);
                *(uint32_t*)(Ch + o0) = hp;
                *(uint32_t*)(Cl + o0) = lp;
                split2(v2, v3, hp, lp);
                *(uint32_t*)(Ch + o1) = hp;
                *(uint32_t*)(Cl + o1) = lp;
            }
        }
    }
}

// ---------------------------------------------------------------------------
// Embedding
// ---------------------------------------------------------------------------
__global__ void __launch_bounds__(192) embed_kernel(
    const int* __restrict__ x, const float* __restrict__ emb,
    const float* __restrict__ pos, float* __restrict__ h,
    __nv_bfloat16* __restrict__ hh, __nv_bfloat16* __restrict__ hl)
{
    const int bt  = blockIdx.x;
    const int tok = x[bt];
    const int t   = bt & (TT - 1);
    const float4* e4 = (const float4*)(emb + (size_t)tok * CC);
    const float4* p4 = (const float4*)(pos + (size_t)t   * CC);
    const int i = threadIdx.x;
    float4 a = e4[i], b = p4[i];
    float4 s = make_float4(a.x + b.x, a.y + b.y, a.z + b.z, a.w + b.w);
    ((float4*)(h + (size_t)bt * CC))[i] = s;
    size_t o = (size_t)bt * CC + i * 4;
    uint32_t hp, lp;
    split2(s.x, s.y, hp, lp);
    *(uint32_t*)(hh + o) = hp;     *(uint32_t*)(hl + o) = lp;
    split2(s.z, s.w, hp, lp);
    *(uint32_t*)(hh + o + 2) = hp; *(uint32_t*)(hl + o + 2) = lp;
}

// ---------------------------------------------------------------------------
// HMMA flash attention: 64x64 tiles, 4 warps, bf16 hi/lo split everywhere.
// qkv layout per token: [K | Q | V] each C cols; head h at offset h*64.
// SMEM (64KB dyn): Qh 0 | Ql 8K | Kh 16K | Kl 24K | Vh 32K | Vl 40K
//                  | Ph 48K | Pl 56K    (each 64 rows x 128B, swz8)
// ---------------------------------------------------------------------------
#define ASMEM (8 * 8192)

__global__ void __launch_bounds__(128) attn_hmma_kernel(
    const __nv_bfloat16* __restrict__ qkvh,
    const __nv_bfloat16* __restrict__ qkvl,
    __nv_bfloat16* __restrict__ outh, __nv_bfloat16* __restrict__ outl)
{
    extern __shared__ __align__(128) char asmem[];
    const int tid  = threadIdx.x;
    const int lane = tid & 31, wid = tid >> 5;
    const int g    = lane >> 2, t = lane & 3;
    const int qtile = blockIdx.x, bh = blockIdx.y;
    const int b = bh / HH, h = bh % HH;
    const int qb = qtile << 6;
    const uint32_t S = smem_u32(asmem);
    const size_t bbase = (size_t)b * TT * 3 * CC;

    auto stage64 = [&](uint32_t off, const __nv_bfloat16* src,
                       int tok0, int coff) {
#pragma unroll
        for (int i = 0; i < 4; i++) {
            int idx = tid + (i << 7);            // 0..511
            int row = idx >> 3, chk = idx & 7;
            const __nv_bfloat16* sp = src + bbase
                + (size_t)(tok0 + row) * (3 * CC) + coff + chk * 8;
            *(uint4*)(asmem + off + swz8(row, chk)) = *(const uint4*)sp;
        }
    };

    // stage Q once (hi/lo)
    stage64(0,    qkvh, qb, CC + h * 64);
    stage64(8192, qkvl, qb, CC + h * 64);
    __syncthreads();

    // Q fragments in registers: rows wid*16..+15, 4 k16-steps
    uint32_t qh[4][4], ql[4][4];
    {
        int row = wid * 16 + (lane & 15);
        int kh  = lane >> 4;
#pragma unroll
        for (int ks = 0; ks < 4; ks++) {
            uint32_t ao = swz8(row, ks * 2 + kh);
            ldsm4(qh[ks], S + 0 + ao);
            ldsm4(ql[ks], S + 8192 + ao);
        }
    }

    float O[8][4];
#pragma unroll
    for (int ni = 0; ni < 8; ni++)
#pragma unroll
        for (int r = 0; r < 4; r++) O[ni][r] = 0.f;
    float m0 = -1e30f, m1 = -1e30f, l0 = 0.f, l1 = 0.f;

    const int row0a = qb + wid * 16 + g;        // absolute q rows
    const int row1a = row0a + 8;

    for (int kt = 0; kt <= qtile; kt++) {
        const int kb = kt << 6;
        __syncthreads();                        // prior iter reads done
        stage64(16384, qkvh, kb, h * 64);               // Kh
        stage64(24576, qkvl, kb, h * 64);               // Kl
        stage64(32768, qkvh, kb, 2 * CC + h * 64);      // Vh
        stage64(40960, qkvl, kb, 2 * CC + h * 64);      // Vl
        __syncthreads();

        // S = Q K^T (3-MMA split)
        float sa[8][4];
#pragma unroll
        for (int ni = 0; ni < 8; ni++)
#pragma unroll
            for (int r = 0; r < 4; r++) sa[ni][r] = 0.f;

        {
            int brow = (lane & 7) + ((lane >> 4) << 3);
            int bkh  = (lane >> 3) & 1;
#pragma unroll
            for (int ks = 0; ks < 4; ks++) {
#pragma unroll
                for (int nip = 0; nip < 4; nip++) {
                    uint32_t bo = swz8(nip * 16 + brow, ks * 2 + bkh);
                    uint32_t kh_[4], kl_[4];
                    ldsm4(kh_, S + 16384 + bo);
                    ldsm4(kl_, S + 24576 + bo);
                    mma16816(sa[2 * nip],     qh[ks], kh_[0], kh_[1]);
                    mma16816(sa[2 * nip],     qh[ks], kl_[0], kl_[1]);
                    mma16816(sa[2 * nip],     ql[ks], kh_[0], kh_[1]);
                    mma16816(sa[2 * nip + 1], qh[ks], kh_[2], kh_[3]);
                    mma16816(sa[2 * nip + 1], qh[ks], kl_[2], kl_[3]);
                    mma16816(sa[2 * nip + 1], ql[ks], kh_[2], kh_[3]);
                }
            }
        }

        // scale + causal mask
        const bool diag = (kt == qtile);
#pragma unroll
        for (int ni = 0; ni < 8; ni++) {
            int c0 = kb + ni * 8 + t * 2, c1 = c0 + 1;
            sa[ni][0] *= 0.125f; sa[ni][1] *= 0.125f;
            sa[ni][2] *= 0.125f; sa[ni][3] *= 0.125f;
            if (diag) {
                if (c0 > row0a) sa[ni][0] = -1e30f;
                if (c1 > row0a) sa[ni][1] = -1e30f;
                if (c0 > row1a) sa[ni][2] = -1e30f;
                if (c1 > row1a) sa[ni][3] = -1e30f;
            }
        }

        // online softmax
        float pm0 = -1e30f, pm1 = -1e30f;
#pragma unroll
        for (int ni = 0; ni < 8; ni++) {
            pm0 = fmaxf(pm0, fmaxf(sa[ni][0], sa[ni][1]));
            pm1 = fmaxf(pm1, fmaxf(sa[ni][2], sa[ni][3]));
        }
#pragma unroll
        for (int o = 1; o < 4; o <<= 1) {
            pm0 = fmaxf(pm0, __shfl_xor_sync(0xffffffffu, pm0, o));
            pm1 = fmaxf(pm1, __shfl_xor_sync(0xffffffffu, pm1, o));
        }
        float mn0 = fmaxf(m0, pm0), mn1 = fmaxf(m1, pm1);
        float a0 = __expf(m0 - mn0), a1 = __expf(m1 - mn1);
        m0 = mn0; m1 = mn1;

        float rs0 = 0.f, rs1 = 0.f;
        const int prow0 = wid * 16 + g, prow1 = prow0 + 8;
#pragma unroll
        for (int ni = 0; ni < 8; ni++) {
            float p0 = __expf(sa[ni][0] - mn0);
            float p1 = __expf(sa[ni][1] - mn0);
            float p2 = __expf(sa[ni][2] - mn1);
            float p3 = __expf(sa[ni][3] - mn1);
            rs0 += p0 + p1; rs1 += p2 + p3;
            uint32_t hp, lp;
            uint32_t po0 = swz8(prow0, ni ^ 0) - ((ni ^ 0) << 4)
                         + (((ni ^ (prow0 & 7))) << 4) ;  // placeholder no
            (void)po0;
            split2(p0, p1, hp, lp);
            *(uint32_t*)(asmem + 49152 + (prow0 << 7)
                         + ((ni ^ (prow0 & 7)) << 4) + t * 4) = hp;
            *(uint32_t*)(asmem + 57344 + (prow0 << 7)
                         + ((ni ^ (prow0 & 7)) << 4) + t * 4) = lp;
            split2(p2, p3, hp, lp);
            *(uint32_t*)(asmem + 49152 + (prow1 << 7)
                         + ((ni ^ (prow1 & 7)) << 4) + t * 4) = hp;
            *(uint32_t*)(asmem + 57344 + (prow1 << 7)
                         + ((ni ^ (prow1 & 7)) << 4) + t * 4) = lp;
        }
#pragma unroll
        for (int o = 1; o < 4; o <<= 1) {
            rs0 += __shfl_xor_sync(0xffffffffu, rs0, o);
            rs1 += __shfl_xor_sync(0xffffffffu, rs1, o);
        }
        l0 = l0 * a0 + rs0;
        l1 = l1 * a1 + rs1;
#pragma unroll
        for (int ni = 0; ni < 8; ni++) {
            O[ni][0] *= a0; O[ni][1] *= a0;
            O[ni][2] *= a1; O[ni][3] *= a1;
        }
        __syncwarp();

        // O += P V (3-MMA split); V^T fragments via ldsm.trans
        {
            int arow = wid * 16 + (lane & 15);
            int akh2 = lane >> 4;
            int vrow = (lane & 7) + (((lane >> 3) & 1) << 3);
            int vch  = lane >> 4;
#pragma unroll
            for (int ks = 0; ks < 4; ks++) {
                uint32_t ao = swz8(arow, ks * 2 + akh2);
                uint32_t ph_[4], pl_[4];
                ldsm4(ph_, S + 49152 + ao);
                ldsm4(pl_, S + 57344 + ao);
#pragma unroll
                for (int nip = 0; nip < 4; nip++) {
                    uint32_t vo = swz8(ks * 16 + vrow, nip * 2 + vch);
                    uint32_t vh_[4], vl_[4];
                    ldsm4t(vh_, S + 32768 + vo);
                    ldsm4t(vl_, S + 40960 + vo);
                    mma16816(O[2 * nip],     ph_, vh_[0], vh_[1]);
                    mma16816(O[2 * nip],     ph_, vl_[0], vl_[1]);
                    mma16816(O[2 * nip],     pl_, vh_[0], vh_[1]);
                    mma16816(O[2 * nip + 1], ph_, vh_[2], vh_[3]);
                    mma16816(O[2 * nip + 1], ph_, vl_[2], vl_[3]);
                    mma16816(O[2 * nip + 1], pl_, vh_[2], vh_[3]);
                }
            }
        }
    }

    // write normalized output (hi/lo)
    float inv0 = 1.0f / l0, inv1 = 1.0f / l1;
    const size_t gr0 = ((size_t)b * TT + row0a) * CC + h * 64;
    const size_t gr1 = ((size_t)b * TT + row1a) * CC + h * 64;
#pragma unroll
    for (int ni = 0; ni < 8; ni++) {
        int col = ni * 8 + t * 2;
        uint32_t hp, lp;
        split2(O[ni][0] * inv0, O[ni][1] * inv0, hp, lp);
        *(uint32_t*)(outh + gr0 + col) = hp;
        *(uint32_t*)(outl + gr0 + col) = lp;
        split2(O[ni][2] * inv1, O[ni][3] * inv1, hp, lp);
        *(uint32_t*)(outh + gr1 + col) = hp;
        *(uint32_t*)(outl + gr1 + col) = lp;
    }
}

// ---------------------------------------------------------------------------
// Fused LayerNorm + residual
// ---------------------------------------------------------------------------
__global__ void __launch_bounds__(256) ln_res_kernel(
    const float* __restrict__ y, const float* __restrict__ g,
    const float* __restrict__ be, float* __restrict__ h,
    __nv_bfloat16* __restrict__ hh, __nv_bfloat16* __restrict__ hl)
{
    __shared__ float red1[8];
    __shared__ float red2[8];
    const int row = blockIdx.x;
    const int tid = threadIdx.x;
    const float* yr = y + (size_t)row * CC;

    float v0 = yr[tid], v1 = yr[tid + 256], v2 = yr[tid + 512];
    float s = v0 + v1 + v2;
#pragma unroll
    for (int o = 16; o; o >>= 1) s += __shfl_xor_sync(0xffffffffu, s, o);
    if ((tid & 31) == 0) red1[tid >> 5] = s;
    __syncthreads();
    float tot = 0.f;
#pragma unroll
    for (int i = 0; i < 8; i++) tot += red1[i];
    float mu = tot * (1.0f / 768.0f);

    float d0 = v0 - mu, d1 = v1 - mu, d2 = v2 - mu;
    float q = d0 * d0 + d1 * d1 + d2 * d2;
#pragma unroll
    for (int o = 16; o; o >>= 1) q += __shfl_xor_sync(0xffffffffu, q, o);
    if ((tid & 31) == 0) red2[tid >> 5] = q;
    __syncthreads();
    float qt = 0.f;
#pragma unroll
    for (int i = 0; i < 8; i++) qt += red2[i];
    float rstd = rsqrtf(qt * (1.0f / 768.0f) + 1e-5f);

    float* hr = h + (size_t)row * CC;
    size_t ob = (size_t)row * CC;
#pragma unroll
    for (int p = 0; p < 3; p++) {
        int c = tid + p * 256;
        float dd = (p == 0) ? d0 : (p == 1) ? d1 : d2;
        float nv = hr[c] + dd * rstd * g[c] + be[c];
        hr[c] = nv;
        __nv_bfloat16 hb = __float2bfloat16_rn(nv);
        hh[ob + c] = hb;
        hl[ob + c] = __float2bfloat16_rn(nv - __bfloat162float(hb));
    }
}

// ---------------------------------------------------------------------------
// Launch
// ---------------------------------------------------------------------------
#define SM128 (3 * (2 * 128 * 64 + 2 * 128 * 64))   // 98304
#define SM64  (3 * (2 * 128 * 64 + 2 * 64 * 64))    // 73728

extern "C" void kernel_launch(void* const* d_in, const int* in_sizes, int n_in,
                              void* d_out, int out_size)
{
    const int*   x     = (const int*)  d_in[0];
    const float* embed = (const float*)d_in[1];
    const float* pos   = (const float*)d_in[2];
    const float* Wqkv  = (const float*)d_in[3];
    const float* bqkv  = (const float*)d_in[4];
    const float* W1a   = (const float*)d_in[5];
    const float* b1a   = (const float*)d_in[6];
    const float* W2a   = (const float*)d_in[7];
    const float* b2a   = (const float*)d_in[8];
    const float* g1    = (const float*)d_in[9];
    const float* beta1 = (const float*)d_in[10];
    const float* W1b   = (const float*)d_in[11];
    const float* b1b   = (const float*)d_in[12];
    const float* W2b   = (const float*)d_in[13];
    const float* b2b   = (const float*)d_in[14];
    const float* g2    = (const float*)d_in[15];
    const float* beta2 = (const float*)d_in[16];
    const float* lmW   = (const float*)d_in[17];
    const float* lmb   = (const float*)d_in[18];
    float* out = (float*)d_out;

    float *h, *tmp;
    __nv_bfloat16 *hh, *hl, *qvh, *qvl, *ath, *atl, *mih, *mil;
    cudaGetSymbolAddress((void**)&h,    g_h);
    cudaGetSymbolAddress((void**)&tmp,  g_tmp);
    cudaGetSymbolAddress((void**)&hh,   g_hh);
    cudaGetSymbolAddress((void**)&hl,   g_hl);
    cudaGetSymbolAddress((void**)&qvh,  g_qvh);
    cudaGetSymbolAddress((void**)&qvl,  g_qvl);
    cudaGetSymbolAddress((void**)&ath,  g_ath);
    cudaGetSymbolAddress((void**)&atl,  g_atl);
    cudaGetSymbolAddress((void**)&mih,  g_mih);
    cudaGetSymbolAddress((void**)&mil,  g_mil);

    __nv_bfloat16 *wqh, *wql, *w1ah, *w1al, *w2ah, *w2al,
                  *w1bh, *w1bl, *w2bh, *w2bl, *lmh, *lml;
    cudaGetSymbolAddress((void**)&wqh,  g_wqkv_h);
    cudaGetSymbolAddress((void**)&wql,  g_wqkv_l);
    cudaGetSymbolAddress((void**)&w1ah, g_w1a_h);
    cudaGetSymbolAddress((void**)&w1al, g_w1a_l);
    cudaGetSymbolAddress((void**)&w2ah, g_w2a_h);
    cudaGetSymbolAddress((void**)&w2al, g_w2a_l);
    cudaGetSymbolAddress((void**)&w1bh, g_w1b_h);
    cudaGetSymbolAddress((void**)&w1bl, g_w1b_l);
    cudaGetSymbolAddress((void**)&w2bh, g_w2b_h);
    cudaGetSymbolAddress((void**)&w2bl, g_w2b_l);
    cudaGetSymbolAddress((void**)&lmh,  g_lm_h);
    cudaGetSymbolAddress((void**)&lml,  g_lm_l);

    cudaFuncSetAttribute(hgemm_kernel<0,0,1,128>,
        cudaFuncAttributeMaxDynamicSharedMemorySize, SM128);
    cudaFuncSetAttribute(hgemm_kernel<1,0,1,128>,
        cudaFuncAttributeMaxDynamicSharedMemorySize, SM128);
    cudaFuncSetAttribute(hgemm_kernel<0,1,0,128>,
        cudaFuncAttributeMaxDynamicSharedMemorySize, SM128);
    cudaFuncSetAttribute(hgemm_kernel<0,1,0,64>,
        cudaFuncAttributeMaxDynamicSharedMemorySize, SM64);
    cudaFuncSetAttribute(attn_hmma_kernel,
        cudaFuncAttributeMaxDynamicSharedMemorySize, ASMEM);

    const dim3 cb(32, 8);
    convert_w_kernel<<<dim3(3 * CC / 32, CC / 32, LNUM), cb>>>(
        Wqkv, wqh, wql, CC, 3 * CC);
    convert_w2_kernel<<<dim3(FFF / 32, CC / 32, 2 * LNUM), cb>>>(
        W1a, W1b, w1ah, w1al, w1bh, w1bl, CC, FFF);
    convert_w2_kernel<<<dim3(CC / 32, FFF / 32, 2 * LNUM), cb>>>(
        W2a, W2b, w2ah, w2al, w2bh, w2bl, FFF, CC);
    convert_w_kernel<<<dim3(VV / 32, CC / 32, 1), cb>>>(lmW, lmh, lml, CC, VV);
    embed_kernel<<<BT, 192>>>(x, embed, pos, h, hh, hl);

    const dim3 grid_qkv (3 * CC / 128, BT / 128);
    const dim3 grid_ffn1(FFF / 128,    BT / 128);
    const dim3 grid_ffn2(CC / 64,      BT / 128);
    const dim3 grid_lm  (VV / 128,     BT / 128);
    const dim3 grid_attn(TT / 64, BB * HH);

    for (int l = 0; l < LNUM; l++) {
        hgemm_kernel<0,0,1,128><<<grid_qkv, 256, SM128>>>(
            hh, hl, wqh + (size_t)l * 3 * CC * CC, wql + (size_t)l * 3 * CC * CC,
            bqkv + (size_t)l * 3 * CC, nullptr, qvh, qvl, 3 * CC, CC);
        attn_hmma_kernel<<<grid_attn, 128, ASMEM>>>(qvh, qvl, ath, atl);
        hgemm_kernel<1,0,1,128><<<grid_ffn1, 256, SM128>>>(
            ath, atl, w1ah + (size_t)l * CC * FFF, w1al + (size_t)l * CC * FFF,
            b1a + (size_t)l * FFF, nullptr, mih, mil, FFF, CC);
        hgemm_kernel<0,1,0,64><<<grid_ffn2, 256, SM64>>>(
            mih, mil, w2ah + (size_t)l * CC * FFF, w2al + (size_t)l * CC * FFF,
            b2a + (size_t)l * CC, tmp, nullptr, nullptr, CC, FFF);
        ln_res_kernel<<<BT, 256>>>(tmp, g1 + (size_t)l * CC,
                                   beta1 + (size_t)l * CC, h, hh, hl);
        hgemm_kernel<1,0,1,128><<<grid_ffn1, 256, SM128>>>(
            hh, hl, w1bh + (size_t)l * CC * FFF, w1bl + (size_t)l * CC * FFF,
            b1b + (size_t)l * FFF, nullptr, mih, mil, FFF, CC);
        hgemm_kernel<0,1,0,64><<<grid_ffn2, 256, SM64>>>(
            mih, mil, w2bh + (size_t)l * CC * FFF, w2bl + (size_t)l * CC * FFF,
            b2b + (size_t)l * CC, tmp, nullptr, nullptr, CC, FFF);
        ln_res_kernel<<<BT, 256>>>(tmp, g2 + (size_t)l * CC,
                                   beta2 + (size_t)l * CC, h, hh, hl);
    }

    hgemm_kernel<0,1,0,128><<<grid_lm, 256, SM128>>>(
        hh, hl, lmh, lml, lmb, out, nullptr, nullptr, VV, CC);
}